// round 1
// baseline (speedup 1.0000x reference)
#include <cuda_runtime.h>

#define Bn   64
#define Nn   512
#define Tt   8
#define DINd 2
#define Hh   256
#define Ll   3
#define Ee   8192
#define Mm   128
#define Pout 24
#define EPSf 1e-5f

// ---------------- scratch (allocation-free) ----------------
__device__ float g_h   [Bn*Nn*Hh];   // encoder output (residual)
__device__ float g_hs  [Bn*Nn*Hh];   // h_social (layer input/output)
__device__ float g_xt  [Bn*Nn*Hh];   // x @ theta
__device__ float g_hc  [Bn*Nn*Hh];   // conv output pre-BN
__device__ float g_msg [Bn*Mm*Hh];   // hyperedge messages
__device__ float g_mean[Bn*Hh];
__device__ float g_var [Bn*Hh];
__device__ float g_invb[Bn*Mm];
__device__ float g_invd[Bn*Nn];
__device__ int   g_cntm[Bn*Mm];
__device__ int   g_cntn[Bn*Nn];

// ---------------- encoder: relu(obs @ Wenc + b), mean over T ----------------
__global__ void k_encoder(const float* __restrict__ obs,
                          const float* __restrict__ Wenc,
                          const float* __restrict__ benc) {
    int bn = blockIdx.x;          // b*N + n
    int h  = threadIdx.x;         // 0..255
    __shared__ float srow[Tt*DINd];
    if (h < Tt*DINd) srow[h] = obs[bn*Tt*DINd + h];
    __syncthreads();
    float w0 = Wenc[h], w1 = Wenc[Hh + h], bb = benc[h];
    float acc = 0.f;
#pragma unroll
    for (int t = 0; t < Tt; t++) {
        float v = fmaf(srow[2*t], w0, fmaf(srow[2*t+1], w1, bb));
        acc += fmaxf(v, 0.f);
    }
    float r = acc * (1.f / Tt);
    g_h [bn*Hh + h] = r;
    g_hs[bn*Hh + h] = r;
}

// ---------------- degrees ----------------
__global__ void k_zero_cnt() {
    int i = blockIdx.x * blockDim.x + threadIdx.x;
    if (i < Bn*Mm) g_cntm[i] = 0;
    if (i < Bn*Nn) g_cntn[i] = 0;
}
__global__ void k_degree(const int* __restrict__ idx) {
    int i = blockIdx.x * blockDim.x + threadIdx.x;   // b*E + e
    int b = i / Ee, e = i - b*Ee;
    int n = idx[b*2*Ee + e];
    int m = idx[b*2*Ee + Ee + e];
    atomicAdd(&g_cntn[b*Nn + n], 1);
    atomicAdd(&g_cntm[b*Mm + m], 1);
}
__global__ void k_invdeg() {
    int i = blockIdx.x * blockDim.x + threadIdx.x;
    if (i < Bn*Mm) g_invb[i] = 1.f / fmaxf((float)g_cntm[i], 1.f);
    if (i < Bn*Nn) g_invd[i] = 1.f / fmaxf((float)g_cntn[i], 1.f);
}

// ---------------- batched SGEMM: xt[b] = hs[b] (512x256) @ theta (256x256) ----------------
__global__ void k_gemm(const float* __restrict__ theta) {
    __shared__ float As[16][68];
    __shared__ float Bs[16][68];
    int tid  = threadIdx.x;                  // 256
    int row0 = blockIdx.y * 64;
    int col0 = blockIdx.x * 64;
    const float* Ab = g_hs + (size_t)blockIdx.z * (Nn*Hh);
    float*       Cb = g_xt + (size_t)blockIdx.z * (Nn*Hh);
    int ty = tid >> 4, tx = tid & 15;
    float acc[4][4] = {};
    for (int kk = 0; kk < Hh; kk += 16) {
        {   // A tile: 64 rows x 16 k (store transposed)
            int m  = tid >> 2;
            int k4 = (tid & 3) * 4;
            float4 v = *reinterpret_cast<const float4*>(&Ab[(row0 + m)*Hh + kk + k4]);
            As[k4+0][m] = v.x; As[k4+1][m] = v.y; As[k4+2][m] = v.z; As[k4+3][m] = v.w;
        }
        {   // B tile: 16 k x 64 cols
            int k  = tid >> 4;
            int n4 = (tid & 15) * 4;
            float4 v = *reinterpret_cast<const float4*>(&theta[(kk + k)*Hh + col0 + n4]);
            *reinterpret_cast<float4*>(&Bs[k][n4]) = v;
        }
        __syncthreads();
#pragma unroll
        for (int k = 0; k < 16; k++) {
            float4 a4 = *reinterpret_cast<const float4*>(&As[k][ty*4]);
            float4 b4 = *reinterpret_cast<const float4*>(&Bs[k][tx*4]);
            float a[4] = {a4.x, a4.y, a4.z, a4.w};
            float b[4] = {b4.x, b4.y, b4.z, b4.w};
#pragma unroll
            for (int i = 0; i < 4; i++)
#pragma unroll
                for (int j = 0; j < 4; j++)
                    acc[i][j] = fmaf(a[i], b[j], acc[i][j]);
        }
        __syncthreads();
    }
#pragma unroll
    for (int i = 0; i < 4; i++) {
        float4 v = make_float4(acc[i][0], acc[i][1], acc[i][2], acc[i][3]);
        *reinterpret_cast<float4*>(&Cb[(row0 + ty*4 + i)*Hh + col0 + tx*4]) = v;
    }
}

// ---------------- msg[b,m,:] = (1/max(bdeg,1)) * sum_{e: edge(e)=m} xt[b,node(e),:] ----------------
__global__ void k_msg(const int* __restrict__ idx) {
    __shared__ float acc[Mm][64];
    int b     = blockIdx.x;
    int hbase = blockIdx.y * 64;
    int tid   = threadIdx.x;      // 256
    for (int i = tid; i < Mm*64; i += 256) (&acc[0][0])[i] = 0.f;
    __syncthreads();
    int col  = tid & 63;
    int esub = tid >> 6;          // 0..3
    const int* nodes = idx + b*2*Ee;
    const int* edges = nodes + Ee;
    const float* xb  = g_xt + (size_t)b * (Nn*Hh) + hbase;
    for (int base = 0; base < Ee; base += 4) {
        int e = base + esub;
        int n = __ldg(&nodes[e]);
        int m = __ldg(&edges[e]);
        atomicAdd(&acc[m][col], xb[(size_t)n*Hh + col]);
    }
    __syncthreads();
    float* mb = g_msg + (size_t)b * (Mm*Hh) + hbase;
    for (int i = tid; i < Mm*64; i += 256) {
        int m = i >> 6, c = i & 63;
        mb[(size_t)m*Hh + c] = acc[m][c] * g_invb[b*Mm + m];
    }
}

// ---------------- hc[b,n,:] = (1/max(ddeg,1)) * sum_{e: node(e)=n} msg[b,edge(e),:] + bias ----------------
__global__ void k_nodeagg(const int* __restrict__ idx,
                          const float* __restrict__ cbias, int l) {
    __shared__ float acc[Nn][16];
    int b     = blockIdx.x;
    int hbase = blockIdx.y * 16;
    int tid   = threadIdx.x;      // 256
    for (int i = tid; i < Nn*16; i += 256) (&acc[0][0])[i] = 0.f;
    __syncthreads();
    int col  = tid & 15;
    int esub = tid >> 4;          // 0..15
    const int* nodes = idx + b*2*Ee;
    const int* edges = nodes + Ee;
    const float* mb  = g_msg + (size_t)b * (Mm*Hh) + hbase;
    for (int base = 0; base < Ee; base += 16) {
        int e = base + esub;
        int n = __ldg(&nodes[e]);
        int m = __ldg(&edges[e]);
        atomicAdd(&acc[n][col], mb[(size_t)m*Hh + col]);
    }
    __syncthreads();
    float* hcb = g_hc + (size_t)b * (Nn*Hh) + hbase;
    for (int i = tid; i < Nn*16; i += 256) {
        int n = i >> 4, c = i & 15;
        hcb[(size_t)n*Hh + c] = acc[n][c] * g_invd[b*Nn + n] + cbias[l*Hh + hbase + c];
    }
}

// ---------------- BN stats over node dim ----------------
__global__ void k_bnstats() {
    int b = blockIdx.x;
    int h = threadIdx.x;          // 256
    const float* base = g_hc + (size_t)b * (Nn*Hh);
    float s = 0.f, sq = 0.f;
#pragma unroll 4
    for (int n = 0; n < Nn; n++) {
        float v = base[(size_t)n*Hh + h];
        s += v; sq = fmaf(v, v, sq);
    }
    float mean = s * (1.f / Nn);
    g_mean[b*Hh + h] = mean;
    g_var [b*Hh + h] = sq * (1.f / Nn) - mean*mean;
}

// ---------------- BN apply + relu -> h_social ----------------
__global__ void k_bnapply(const float* __restrict__ gam,
                          const float* __restrict__ bet, int l) {
    int i = blockIdx.x * 256 + threadIdx.x;   // over B*N*H
    int h = i & (Hh - 1);
    int b = i / (Nn*Hh);
    float mean = g_mean[b*Hh + h];
    float var  = g_var [b*Hh + h];
    float v = (g_hc[i] - mean) * rsqrtf(var + EPSf) * gam[l*Hh + h] + bet[l*Hh + h];
    g_hs[i] = fmaxf(v, 0.f);
}

// ---------------- decoder: out = (h + h_social) @ Wdec + bdec ----------------
__global__ void k_decoder(const float* __restrict__ Wdec,
                          const float* __restrict__ bdec,
                          float* __restrict__ out) {
    int bn  = blockIdx.x;
    int tid = threadIdx.x;        // 128
    __shared__ float x[Hh];
    for (int i = tid; i < Hh; i += 128) x[i] = g_h[(size_t)bn*Hh + i] + g_hs[(size_t)bn*Hh + i];
    __syncthreads();
    int w = tid >> 5, lane = tid & 31;   // warp w handles outputs [w*6, w*6+6)
    float a[6] = {0,0,0,0,0,0};
    for (int k = lane; k < Hh; k += 32) {
        float xv = x[k];
        const float* wr = Wdec + (size_t)k*Pout + w*6;
#pragma unroll
        for (int j = 0; j < 6; j++) a[j] = fmaf(xv, wr[j], a[j]);
    }
#pragma unroll
    for (int j = 0; j < 6; j++)
        for (int off = 16; off; off >>= 1)
            a[j] += __shfl_down_sync(0xffffffffu, a[j], off);
    if (lane == 0) {
#pragma unroll
        for (int j = 0; j < 6; j++)
            out[(size_t)bn*Pout + w*6 + j] = a[j] + bdec[w*6 + j];
    }
}

// ---------------- launch ----------------
extern "C" void kernel_launch(void* const* d_in, const int* in_sizes, int n_in,
                              void* d_out, int out_size) {
    const float* obs    = (const float*)d_in[0];
    const int*   idx    = (const int*)  d_in[1];
    const float* Wenc   = (const float*)d_in[2];
    const float* benc   = (const float*)d_in[3];
    const float* thetas = (const float*)d_in[4];
    const float* cbias  = (const float*)d_in[5];
    const float* gam    = (const float*)d_in[6];
    const float* bet    = (const float*)d_in[7];
    const float* Wdec   = (const float*)d_in[8];
    const float* bdec   = (const float*)d_in[9];
    float* out = (float*)d_out;

    k_encoder<<<Bn*Nn, Hh>>>(obs, Wenc, benc);
    k_zero_cnt<<<(Bn*Nn + 255)/256, 256>>>();
    k_degree<<<Bn*Ee/256, 256>>>(idx);
    k_invdeg<<<(Bn*Nn + 255)/256, 256>>>();

    for (int l = 0; l < Ll; l++) {
        k_gemm<<<dim3(Hh/64, Nn/64, Bn), 256>>>(thetas + (size_t)l*Hh*Hh);
        k_msg<<<dim3(Bn, Hh/64), 256>>>(idx);
        k_nodeagg<<<dim3(Bn, Hh/16), 256>>>(idx, cbias, l);
        k_bnstats<<<Bn, Hh>>>();
        k_bnapply<<<Bn*Nn*Hh/256, 256>>>(gam, bet, l);
    }

    k_decoder<<<Bn*Nn, 128>>>(Wdec, bdec, out);
}

// round 2
// speedup vs baseline: 5.0851x; 5.0851x over previous
#include <cuda_runtime.h>

#define Bn   64
#define Nn   512
#define Tt   8
#define DINd 2
#define Hh   256
#define Ll   3
#define Ee   8192
#define Mm   128
#define Pout 24
#define EPSf 1e-5f

// ---------------- scratch (allocation-free) ----------------
__device__ float g_h   [Bn*Nn*Hh];   // encoder output (residual)
__device__ float g_hs  [Bn*Nn*Hh];   // h_social (layer input/output)
__device__ float g_hc  [Bn*Nn*Hh];   // conv output pre-BN
__device__ float g_Y   [Bn*Mm*Hh];   // Hc^T @ hs
__device__ float g_Z   [Bn*Mm*Hh];   // Y @ theta
__device__ float g_Hc  [Bn*Nn*Mm];   // dense incidence counts, Dinv-scaled
__device__ float g_HcT [Bn*Mm*Nn];   // transpose, Binv-scaled
__device__ float g_sum [Bn*Hh];      // BN partial sums
__device__ float g_sq  [Bn*Hh];

// ---------------- encoder: relu(obs @ Wenc + b), mean over T ----------------
__global__ void k_encoder(const float* __restrict__ obs,
                          const float* __restrict__ Wenc,
                          const float* __restrict__ benc) {
    int bn = blockIdx.x;
    int h  = threadIdx.x;
    __shared__ float srow[Tt*DINd];
    if (h < Tt*DINd) srow[h] = obs[bn*Tt*DINd + h];
    __syncthreads();
    float w0 = Wenc[h], w1 = Wenc[Hh + h], bb = benc[h];
    float acc = 0.f;
#pragma unroll
    for (int t = 0; t < Tt; t++) {
        float v = fmaf(srow[2*t], w0, fmaf(srow[2*t+1], w1, bb));
        acc += fmaxf(v, 0.f);
    }
    float r = acc * (1.f / Tt);
    g_h [bn*Hh + h] = r;
    g_hs[bn*Hh + h] = r;
}

// ---------------- dense incidence build ----------------
__global__ void k_zero_dense() {
    int i = blockIdx.x * blockDim.x + threadIdx.x;   // over Bn*Nn*Mm
    g_Hc[i]  = 0.f;
    g_HcT[i] = 0.f;
}
__global__ void k_build(const int* __restrict__ idx) {
    int i = blockIdx.x * blockDim.x + threadIdx.x;   // b*E + e
    int b = i >> 13, e = i & (Ee - 1);
    int n = idx[b*2*Ee + e];
    int m = idx[b*2*Ee + Ee + e];
    atomicAdd(&g_Hc [((size_t)b*Nn + n)*Mm + m], 1.f);
    atomicAdd(&g_HcT[((size_t)b*Mm + m)*Nn + n], 1.f);
}
// scale HcT rows by 1/max(bdeg,1): warp per row of 512
__global__ void k_scale_m() {
    int row  = blockIdx.x * 8 + (threadIdx.x >> 5);   // 0..Bn*Mm-1
    int lane = threadIdx.x & 31;
    float* p = g_HcT + (size_t)row * Nn;
    float s = 0.f;
#pragma unroll
    for (int k = 0; k < 16; k++) s += p[lane + k*32];
#pragma unroll
    for (int off = 16; off; off >>= 1) s += __shfl_xor_sync(0xffffffffu, s, off);
    float rinv = 1.f / fmaxf(s, 1.f);
#pragma unroll
    for (int k = 0; k < 16; k++) p[lane + k*32] *= rinv;
}
// scale Hc rows by 1/max(ddeg,1): warp per row of 128
__global__ void k_scale_n() {
    int row  = blockIdx.x * 8 + (threadIdx.x >> 5);   // 0..Bn*Nn-1
    int lane = threadIdx.x & 31;
    float* p = g_Hc + (size_t)row * Mm;
    float s = 0.f;
#pragma unroll
    for (int k = 0; k < 4; k++) s += p[lane + k*32];
#pragma unroll
    for (int off = 16; off; off >>= 1) s += __shfl_xor_sync(0xffffffffu, s, off);
    float rinv = 1.f / fmaxf(s, 1.f);
#pragma unroll
    for (int k = 0; k < 4; k++) p[lane + k*32] *= rinv;
}

__global__ void k_zero_stats() {
    int i = blockIdx.x * blockDim.x + threadIdx.x;   // over Bn*Hh
    g_sum[i] = 0.f;
    g_sq[i]  = 0.f;
}

// ---------------- batched SGEMM: C[z] = A[z] @ B[z]  (BM=128, BN=64, BK=16) ----------------
// EPI=0: plain store. EPI=1: +bias, store, and accumulate BN column sums.
template<int EPI>
__global__ void k_gemm_t(const float* __restrict__ Ag, const float* __restrict__ Bg,
                         float* __restrict__ Cg,
                         int K, int lda, int ldb,
                         long strideA, long strideB, long strideC,
                         const float* __restrict__ bias) {
    __shared__ float As[16][132];
    __shared__ float Bs[16][68];
    int tid  = threadIdx.x;                  // 256
    int col0 = blockIdx.x * 64;
    int row0 = blockIdx.y * 128;
    int z    = blockIdx.z;
    const float* A = Ag + (size_t)z * strideA;
    const float* B = Bg + (size_t)z * strideB;
    float*       C = Cg + (size_t)z * strideC;

    int ty = tid >> 4, tx = tid & 15;        // ty 0..15 -> 8 rows, tx 0..15 -> 4 cols
    int ar = tid >> 1;                        // A load row 0..127
    int ak = (tid & 1) * 8;                   // A load k offset 0 or 8
    int br = tid >> 4;                        // B load row 0..15
    int bc = (tid & 15) * 4;                  // B load col

    float acc[8][4] = {};
    for (int kk = 0; kk < K; kk += 16) {
        float4 a0 = *reinterpret_cast<const float4*>(&A[(size_t)(row0 + ar)*lda + kk + ak]);
        float4 a1 = *reinterpret_cast<const float4*>(&A[(size_t)(row0 + ar)*lda + kk + ak + 4]);
        float4 b0 = *reinterpret_cast<const float4*>(&B[(size_t)(kk + br)*ldb + col0 + bc]);
        __syncthreads();
        As[ak+0][ar] = a0.x; As[ak+1][ar] = a0.y; As[ak+2][ar] = a0.z; As[ak+3][ar] = a0.w;
        As[ak+4][ar] = a1.x; As[ak+5][ar] = a1.y; As[ak+6][ar] = a1.z; As[ak+7][ar] = a1.w;
        *reinterpret_cast<float4*>(&Bs[br][bc]) = b0;
        __syncthreads();
#pragma unroll
        for (int k = 0; k < 16; k++) {
            float4 av0 = *reinterpret_cast<const float4*>(&As[k][ty*8]);
            float4 av1 = *reinterpret_cast<const float4*>(&As[k][ty*8 + 4]);
            float4 bv  = *reinterpret_cast<const float4*>(&Bs[k][tx*4]);
            float a[8] = {av0.x, av0.y, av0.z, av0.w, av1.x, av1.y, av1.z, av1.w};
            float b[4] = {bv.x, bv.y, bv.z, bv.w};
#pragma unroll
            for (int i = 0; i < 8; i++)
#pragma unroll
                for (int j = 0; j < 4; j++)
                    acc[i][j] = fmaf(a[i], b[j], acc[i][j]);
        }
    }

    if (EPI == 0) {
#pragma unroll
        for (int i = 0; i < 8; i++) {
            float4 v = make_float4(acc[i][0], acc[i][1], acc[i][2], acc[i][3]);
            *reinterpret_cast<float4*>(&C[(size_t)(row0 + ty*8 + i)*Hh + col0 + tx*4]) = v;
        }
    } else {
        float bb[4];
#pragma unroll
        for (int j = 0; j < 4; j++) bb[j] = bias[col0 + tx*4 + j];
        float cs[4] = {}, cq[4] = {};
#pragma unroll
        for (int i = 0; i < 8; i++) {
            float cv[4];
#pragma unroll
            for (int j = 0; j < 4; j++) {
                cv[j] = acc[i][j] + bb[j];
                cs[j] += cv[j];
                cq[j] = fmaf(cv[j], cv[j], cq[j]);
            }
            float4 v = make_float4(cv[0], cv[1], cv[2], cv[3]);
            *reinterpret_cast<float4*>(&C[(size_t)(row0 + ty*8 + i)*Hh + col0 + tx*4]) = v;
        }
        // reduce column sums across ty (16) via smem, then atomics to global
        float* reds = &As[0][0];   // >= 1024 floats
        float* redq = &Bs[0][0];   // >= 1024 floats
        __syncthreads();
#pragma unroll
        for (int j = 0; j < 4; j++) {
            reds[ty*64 + tx*4 + j] = cs[j];
            redq[ty*64 + tx*4 + j] = cq[j];
        }
        __syncthreads();
        if (tid < 64) {
            float s = 0.f, q = 0.f;
#pragma unroll
            for (int t = 0; t < 16; t++) {
                s += reds[t*64 + tid];
                q += redq[t*64 + tid];
            }
            atomicAdd(&g_sum[z*Hh + col0 + tid], s);
            atomicAdd(&g_sq [z*Hh + col0 + tid], q);
        }
    }
}

// ---------------- BN apply + relu -> h_social ----------------
__global__ void k_bnapply(const float* __restrict__ gam,
                          const float* __restrict__ bet, int l) {
    int i = blockIdx.x * 256 + threadIdx.x;   // over B*N*H
    int h = i & (Hh - 1);
    int b = i >> 17;                           // / (Nn*Hh)
    float mean = g_sum[b*Hh + h] * (1.f / Nn);
    float var  = g_sq [b*Hh + h] * (1.f / Nn) - mean*mean;
    float v = (g_hc[i] - mean) * rsqrtf(var + EPSf) * gam[l*Hh + h] + bet[l*Hh + h];
    g_hs[i] = fmaxf(v, 0.f);
}

// ---------------- decoder: out = (h + h_social) @ Wdec + bdec ----------------
__global__ void k_decoder(const float* __restrict__ Wdec,
                          const float* __restrict__ bdec,
                          float* __restrict__ out) {
    __shared__ float Ws[Hh*Pout + 32];
    int tid = threadIdx.x;        // 256 = 8 warps
    for (int i = tid; i < Hh*Pout; i += 256) Ws[i] = Wdec[i];
    __syncthreads();
    int row  = blockIdx.x * 8 + (tid >> 5);
    int lane = tid & 31;
    const float* xh = g_h  + (size_t)row * Hh;
    const float* xs = g_hs + (size_t)row * Hh;
    float xr[8];
#pragma unroll
    for (int j = 0; j < 8; j++) xr[j] = xh[lane + j*32] + xs[lane + j*32];
    float acc = 0.f;
    int wl = (lane < Pout) ? lane : 0;
#pragma unroll 4
    for (int k = 0; k < Hh; k++) {
        float xv = __shfl_sync(0xffffffffu, xr[k >> 5], k & 31);
        acc = fmaf(xv, Ws[k*Pout + wl], acc);
    }
    if (lane < Pout)
        out[(size_t)row*Pout + lane] = acc + bdec[lane];
}

// ---------------- launch ----------------
extern "C" void kernel_launch(void* const* d_in, const int* in_sizes, int n_in,
                              void* d_out, int out_size) {
    const float* obs    = (const float*)d_in[0];
    const int*   idx    = (const int*)  d_in[1];
    const float* Wenc   = (const float*)d_in[2];
    const float* benc   = (const float*)d_in[3];
    const float* thetas = (const float*)d_in[4];
    const float* cbias  = (const float*)d_in[5];
    const float* gam    = (const float*)d_in[6];
    const float* bet    = (const float*)d_in[7];
    const float* Wdec   = (const float*)d_in[8];
    const float* bdec   = (const float*)d_in[9];
    float* out = (float*)d_out;

    const float* pHc  = nullptr;  // device symbols used directly in kernels
    (void)pHc;

    k_encoder<<<Bn*Nn, Hh>>>(obs, Wenc, benc);
    k_zero_dense<<<Bn*Nn*Mm/256, 256>>>();
    k_build<<<Bn*Ee/256, 256>>>(idx);
    k_scale_m<<<Bn*Mm/8, 256>>>();
    k_scale_n<<<Bn*Nn/8, 256>>>();

    // device-symbol addresses for GEMM args
    float *dHc, *dHcT, *dhs, *dY, *dZ, *dhc;
    cudaGetSymbolAddress((void**)&dHc,  g_Hc);
    cudaGetSymbolAddress((void**)&dHcT, g_HcT);
    cudaGetSymbolAddress((void**)&dhs,  g_hs);
    cudaGetSymbolAddress((void**)&dY,   g_Y);
    cudaGetSymbolAddress((void**)&dZ,   g_Z);
    cudaGetSymbolAddress((void**)&dhc,  g_hc);

    for (int l = 0; l < Ll; l++) {
        k_zero_stats<<<Bn*Hh/256, 256>>>();
        // S1: Y[b] (128x256) = HcT_s[b] (128x512) @ hs[b] (512x256)
        k_gemm_t<0><<<dim3(4, 1, Bn), 256>>>(dHcT, dhs, dY,
            512, 512, 256, (long)Mm*Nn, (long)Nn*Hh, (long)Mm*Hh, nullptr);
        // S2: Z[b] (128x256) = Y[b] @ theta_l (256x256)
        k_gemm_t<0><<<dim3(4, 1, Bn), 256>>>(dY, thetas + (size_t)l*Hh*Hh, dZ,
            256, 256, 256, (long)Mm*Hh, 0L, (long)Mm*Hh, nullptr);
        // S3: hc[b] (512x256) = Hc_s[b] (512x128) @ Z[b] + bias  (+ fused BN stats)
        k_gemm_t<1><<<dim3(4, 4, Bn), 256>>>(dHc, dZ, dhc,
            128, 128, 256, (long)Nn*Mm, (long)Mm*Hh, (long)Nn*Hh, cbias + (size_t)l*Hh);
        k_bnapply<<<Bn*Nn*Hh/256, 256>>>(gam, bet, l);
    }

    k_decoder<<<Bn*Nn/8, 256>>>(Wdec, bdec, out);
}

// round 5
// speedup vs baseline: 5.5126x; 1.0841x over previous
#include <cuda_runtime.h>
#include <cstdint>

#define Bn   64
#define Nn   512
#define Tt   8
#define DINd 2
#define Hh   256
#define Ll   3
#define Ee   8192
#define Mm   128
#define Pout 24
#define EPSf 1e-5f

// ---------------- scratch (allocation-free) ----------------
__device__ float g_h      [Bn*Nn*Hh];   // encoder output (residual)
__device__ float g_hs     [Bn*Nn*Hh];   // h_social row-major (decoder input, last layer)
__device__ float g_hsT_hi [Bn*Hh*Nn];   // h_social^T tf32-hi
__device__ float g_hsT_lo [Bn*Hh*Nn];   // h_social^T tf32-lo
__device__ float g_hc     [Bn*Nn*Hh];   // conv output pre-BN (fp32)
__device__ float g_Y_hi   [Bn*Mm*Hh];
__device__ float g_Y_lo   [Bn*Mm*Hh];
__device__ float g_ZT_hi  [Bn*Hh*Mm];
__device__ float g_ZT_lo  [Bn*Hh*Mm];
__device__ float g_Hc     [Bn*Nn*Mm];   // RAW integer counts (tf32-exact)
__device__ float g_HcT    [Bn*Mm*Nn];   // RAW integer counts (tf32-exact)
__device__ float g_thT_hi [Ll*Hh*Hh];
__device__ float g_thT_lo [Ll*Hh*Hh];
__device__ float g_invb   [Bn*Mm];
__device__ float g_invd   [Bn*Nn];
__device__ int   g_cntm   [Bn*Mm];
__device__ int   g_cntn   [Bn*Nn];
__device__ float g_sum    [Bn*Hh];
__device__ float g_sq     [Bn*Hh];

// ================= helpers =================
__device__ __forceinline__ uint32_t smem_u32(const void* p) {
    uint32_t a;
    asm("{ .reg .u64 t; cvta.to.shared.u64 t, %1; cvt.u32.u64 %0, t; }" : "=r"(a) : "l"(p));
    return a;
}
__device__ __forceinline__ float tf32r(float x) {
    uint32_t u;
    asm("cvt.rna.tf32.f32 %0, %1;" : "=r"(u) : "f"(x));
    return __uint_as_float(u);
}
#define CP16(dst, src) asm volatile("cp.async.cg.shared.global [%0], [%1], 16;" :: "r"(dst), "l"(src) : "memory")
#define CPCOMMIT()     asm volatile("cp.async.commit_group;" ::: "memory")
#define CPWAIT1()      asm volatile("cp.async.wait_group 1;" ::: "memory")

__device__ __forceinline__ void mma_tf32(float* c, const uint32_t* a, const uint32_t* b) {
    asm volatile(
        "mma.sync.aligned.m16n8k8.row.col.f32.tf32.tf32.f32 "
        "{%0,%1,%2,%3}, {%4,%5,%6,%7}, {%8,%9}, {%0,%1,%2,%3};"
        : "+f"(c[0]), "+f"(c[1]), "+f"(c[2]), "+f"(c[3])
        : "r"(a[0]), "r"(a[1]), "r"(a[2]), "r"(a[3]), "r"(b[0]), "r"(b[1]));
}

// ================= error-compensated tf32 mma.sync GEMM =================
// C[M x N] = A @ B_hi^T + A @ B_lo^T                  (SPLITA=0, A exact in tf32)
// C[M x N] = A_hi@B_hi^T + A_hi@B_lo^T + A_lo@B_hi^T  (SPLITA=1)
// All operands K-major. Block 128x128, warps 2x4 (64x32), BK=32, cp.async 2-stage.
// Epilogue: optional per-row scale, per-col bias; output fp32 (Cl==null) or
// tf32 hi/lo split (C=hi, Cl=lo).
#define TSTRIDE 36
#define TILE_FLOATS (128 * TSTRIDE)

template<int SPLITA>
__global__ void __launch_bounds__(256, 1)
k_mma2(const float* __restrict__ Ah, const float* __restrict__ Al,
       const float* __restrict__ Bh, const float* __restrict__ Bl,
       float* __restrict__ Cg, float* __restrict__ Clg,
       const float* __restrict__ rowscale, const float* __restrict__ bias,
       int K, int N, long sA, long sB, long sC) {
    extern __shared__ float sm[];
    uint32_t sbase = smem_u32(sm);
    // tile offsets (in floats)
    const int O_AH = 0;
    const int O_AL = SPLITA ? 2 * TILE_FLOATS : 0;
    const int O_BH = (SPLITA ? 4 : 2) * TILE_FLOATS;
    const int O_BL = O_BH + 2 * TILE_FLOATS;

    int tid = threadIdx.x, lane = tid & 31, wid = tid >> 5;
    int wm = wid >> 2, wn = wid & 3;
    int row0 = blockIdx.y * 128, col0 = blockIdx.x * 128;
    int z = blockIdx.z;
    const float* pAh = Ah + (size_t)z * sA;
    const float* pAl = SPLITA ? (Al + (size_t)z * sA) : nullptr;
    const float* pBh = Bh + (size_t)z * sB;
    const float* pBl = Bl + (size_t)z * sB;
    float* C  = Cg  + (size_t)z * sC;
    float* Cl = Clg ? (Clg + (size_t)z * sC) : nullptr;

    int ldr = tid >> 3;                  // 0..31
    int ldc = (tid & 7) * 4;             // 0,4,..28

    float acc[4][4][4];
#pragma unroll
    for (int i = 0; i < 4; i++)
#pragma unroll
        for (int j = 0; j < 4; j++)
#pragma unroll
            for (int q = 0; q < 4; q++) acc[i][j][q] = 0.f;

    int nkb = K >> 5;

#pragma unroll
    for (int s = 0; s < 2; s++) {
        int kk = s * 32;
#pragma unroll
        for (int i = 0; i < 4; i++) {
            int rr = ldr + i * 32;
            size_t go = (size_t)(row0 + rr) * K + kk + ldc;
            size_t gb = (size_t)(col0 + rr) * K + kk + ldc;
            uint32_t so = (uint32_t)(s * TILE_FLOATS + rr * TSTRIDE + ldc) * 4;
            CP16(sbase + O_AH * 4 + so, pAh + go);
            if (SPLITA) CP16(sbase + O_AL * 4 + so, pAl + go);
            CP16(sbase + O_BH * 4 + so, pBh + gb);
            CP16(sbase + O_BL * 4 + so, pBl + gb);
        }
        CPCOMMIT();
    }

    for (int kb = 0; kb < nkb; kb++) {
        int s = kb & 1;
        CPWAIT1();
        __syncthreads();

        const float* At  = sm + O_AH + s * TILE_FLOATS + (wm * 64) * TSTRIDE;
        const float* Atl = sm + O_AL + s * TILE_FLOATS + (wm * 64) * TSTRIDE;
        const float* Bt  = sm + O_BH + s * TILE_FLOATS + (wn * 32) * TSTRIDE;
        const float* Btl = sm + O_BL + s * TILE_FLOATS + (wn * 32) * TSTRIDE;
        int g = lane >> 2, t = lane & 3;

#pragma unroll
        for (int ks = 0; ks < 4; ks++) {
            int kc = ks * 8 + t;
            uint32_t ah[4][4], al[4][4], bh[4][2], bl[4][2];
#pragma unroll
            for (int mf = 0; mf < 4; mf++) {
                const float* p = At + (mf * 16 + g) * TSTRIDE + kc;
                ah[mf][0] = __float_as_uint(p[0]);
                ah[mf][1] = __float_as_uint(p[8 * TSTRIDE]);
                ah[mf][2] = __float_as_uint(p[4]);
                ah[mf][3] = __float_as_uint(p[8 * TSTRIDE + 4]);
                if (SPLITA) {
                    const float* q = Atl + (mf * 16 + g) * TSTRIDE + kc;
                    al[mf][0] = __float_as_uint(q[0]);
                    al[mf][1] = __float_as_uint(q[8 * TSTRIDE]);
                    al[mf][2] = __float_as_uint(q[4]);
                    al[mf][3] = __float_as_uint(q[8 * TSTRIDE + 4]);
                }
            }
#pragma unroll
            for (int nf = 0; nf < 4; nf++) {
                const float* p = Bt + (nf * 8 + g) * TSTRIDE + kc;
                bh[nf][0] = __float_as_uint(p[0]);
                bh[nf][1] = __float_as_uint(p[4]);
                const float* q = Btl + (nf * 8 + g) * TSTRIDE + kc;
                bl[nf][0] = __float_as_uint(q[0]);
                bl[nf][1] = __float_as_uint(q[4]);
            }
#pragma unroll
            for (int mf = 0; mf < 4; mf++)
#pragma unroll
                for (int nf = 0; nf < 4; nf++) {
                    mma_tf32(acc[mf][nf], ah[mf], bl[nf]);
                    if (SPLITA) mma_tf32(acc[mf][nf], al[mf], bh[nf]);
                    mma_tf32(acc[mf][nf], ah[mf], bh[nf]);
                }
        }
        __syncthreads();

        if (kb + 2 < nkb) {
            int kk = (kb + 2) * 32;
#pragma unroll
            for (int i = 0; i < 4; i++) {
                int rr = ldr + i * 32;
                size_t go = (size_t)(row0 + rr) * K + kk + ldc;
                size_t gb = (size_t)(col0 + rr) * K + kk + ldc;
                uint32_t so = (uint32_t)(s * TILE_FLOATS + rr * TSTRIDE + ldc) * 4;
                CP16(sbase + O_AH * 4 + so, pAh + go);
                if (SPLITA) CP16(sbase + O_AL * 4 + so, pAl + go);
                CP16(sbase + O_BH * 4 + so, pBh + gb);
                CP16(sbase + O_BL * 4 + so, pBl + gb);
            }
        }
        CPCOMMIT();
    }

    // epilogue
    int g = lane >> 2, t = lane & 3;
    const float* rsb = rowscale ? rowscale + (size_t)z * (gridDim.y * 128) : nullptr;
#pragma unroll
    for (int mf = 0; mf < 4; mf++) {
        int rr = row0 + wm * 64 + mf * 16 + g;
        float rs0 = rsb ? rsb[rr]     : 1.f;
        float rs1 = rsb ? rsb[rr + 8] : 1.f;
#pragma unroll
        for (int nf = 0; nf < 4; nf++) {
            int cc = col0 + wn * 32 + nf * 8 + t * 2;
            float c0 = acc[mf][nf][0] * rs0, c1 = acc[mf][nf][1] * rs0;
            float c2 = acc[mf][nf][2] * rs1, c3 = acc[mf][nf][3] * rs1;
            if (bias) {
                float b0 = bias[cc], b1 = bias[cc + 1];
                c0 += b0; c1 += b1; c2 += b0; c3 += b1;
            }
            if (Cl) {
                float h0 = tf32r(c0), h1 = tf32r(c1), h2 = tf32r(c2), h3 = tf32r(c3);
                *reinterpret_cast<float2*>(&C [(size_t)rr * N + cc])       = make_float2(h0, h1);
                *reinterpret_cast<float2*>(&C [(size_t)(rr + 8) * N + cc]) = make_float2(h2, h3);
                *reinterpret_cast<float2*>(&Cl[(size_t)rr * N + cc])       = make_float2(tf32r(c0 - h0), tf32r(c1 - h1));
                *reinterpret_cast<float2*>(&Cl[(size_t)(rr + 8) * N + cc]) = make_float2(tf32r(c2 - h2), tf32r(c3 - h3));
            } else {
                *reinterpret_cast<float2*>(&C[(size_t)rr * N + cc])       = make_float2(c0, c1);
                *reinterpret_cast<float2*>(&C[(size_t)(rr + 8) * N + cc]) = make_float2(c2, c3);
            }
        }
    }
}

// ---------------- encoder ----------------
__global__ void k_encoder(const float* __restrict__ obs,
                          const float* __restrict__ Wenc,
                          const float* __restrict__ benc) {
    int bn = blockIdx.x;
    int h  = threadIdx.x;
    int b  = bn >> 9, n = bn & (Nn - 1);
    __shared__ float srow[Tt*DINd];
    if (h < Tt*DINd) srow[h] = obs[bn*Tt*DINd + h];
    __syncthreads();
    float w0 = Wenc[h], w1 = Wenc[Hh + h], bb = benc[h];
    float acc = 0.f;
#pragma unroll
    for (int t = 0; t < Tt; t++) {
        float v = fmaf(srow[2*t], w0, fmaf(srow[2*t+1], w1, bb));
        acc += fmaxf(v, 0.f);
    }
    float r = acc * (1.f / Tt);
    g_h[(size_t)bn*Hh + h] = r;
    float hi = tf32r(r);
    size_t ix = ((size_t)b*Hh + h)*Nn + n;
    g_hsT_hi[ix] = hi;
    g_hsT_lo[ix] = tf32r(r - hi);
}

// ---------------- incidence build (raw counts) ----------------
__global__ void k_zero_dense() {
    int i = blockIdx.x * blockDim.x + threadIdx.x;
    g_Hc[i]  = 0.f;
    g_HcT[i] = 0.f;
}
__global__ void k_zero_small() {
    int i = blockIdx.x * blockDim.x + threadIdx.x;
    if (i < Bn*Mm) g_cntm[i] = 0;
    if (i < Bn*Nn) g_cntn[i] = 0;
}
__global__ void k_build(const int* __restrict__ idx) {
    int i = blockIdx.x * blockDim.x + threadIdx.x;
    int b = i >> 13, e = i & (Ee - 1);
    int n = idx[b*2*Ee + e];
    int m = idx[b*2*Ee + Ee + e];
    atomicAdd(&g_Hc [((size_t)b*Nn + n)*Mm + m], 1.f);
    atomicAdd(&g_HcT[((size_t)b*Mm + m)*Nn + n], 1.f);
    atomicAdd(&g_cntn[b*Nn + n], 1);
    atomicAdd(&g_cntm[b*Mm + m], 1);
}
__global__ void k_invdeg() {
    int i = blockIdx.x * blockDim.x + threadIdx.x;
    if (i < Bn*Mm) g_invb[i] = 1.f / fmaxf((float)g_cntm[i], 1.f);
    if (i < Bn*Nn) g_invd[i] = 1.f / fmaxf((float)g_cntn[i], 1.f);
}

// ---------------- theta transpose (split) ----------------
__global__ void k_trans_theta(const float* __restrict__ thetas) {
    __shared__ float t[32][33];
    int l  = blockIdx.z;
    int x0 = blockIdx.x * 32, y0 = blockIdx.y * 32;
    int tx = threadIdx.x, ty = threadIdx.y;
    const float* src = thetas + (size_t)l * Hh * Hh;
#pragma unroll
    for (int j = 0; j < 4; j++)
        t[ty + j*8][tx] = src[(size_t)(y0 + ty + j*8)*Hh + x0 + tx];
    __syncthreads();
#pragma unroll
    for (int j = 0; j < 4; j++) {
        float v = t[tx][ty + j*8];
        float hi = tf32r(v);
        size_t ix = (size_t)l*Hh*Hh + (size_t)(x0 + ty + j*8)*Hh + y0 + tx;
        g_thT_hi[ix] = hi;
        g_thT_lo[ix] = tf32r(v - hi);
    }
}

// ---------------- BN stats ----------------
__global__ void k_zero_stats() {
    int i = blockIdx.x * blockDim.x + threadIdx.x;
    g_sum[i] = 0.f;
    g_sq[i]  = 0.f;
}
__global__ void k_bnstats() {
    int b = blockIdx.x, part = blockIdx.y;
    int h = threadIdx.x;
    const float* base = g_hc + (size_t)b*Nn*Hh + (size_t)part*128*Hh;
    float s = 0.f, q = 0.f;
#pragma unroll 4
    for (int n = 0; n < 128; n++) {
        float v = base[(size_t)n*Hh + h];
        s += v; q = fmaf(v, v, q);
    }
    atomicAdd(&g_sum[b*Hh + h], s);
    atomicAdd(&g_sq [b*Hh + h], q);
}

// ---------------- BN apply + relu -> hsT split (+ hs row-major on last layer) ----------------
__global__ void k_bnapply_t(const float* __restrict__ gam,
                            const float* __restrict__ bet, int l, int writeRow) {
    __shared__ float t[32][33];
    int b  = blockIdx.z;
    int h0 = blockIdx.x * 32, n0 = blockIdx.y * 32;
    int tx = threadIdx.x, ty = threadIdx.y;
    int h  = h0 + tx;
    float mean = g_sum[b*Hh + h] * (1.f / Nn);
    float var  = g_sq [b*Hh + h] * (1.f / Nn) - mean*mean;
    float rstd = rsqrtf(var + EPSf);
    float gm = gam[l*Hh + h], bt = bet[l*Hh + h];
#pragma unroll
    for (int j = 0; j < 4; j++) {
        int n = n0 + ty + j*8;
        size_t ix = ((size_t)b*Nn + n)*Hh + h;
        float v = fmaxf((g_hc[ix] - mean) * rstd * gm + bt, 0.f);
        if (writeRow) g_hs[ix] = v;
        t[ty + j*8][tx] = v;
    }
    __syncthreads();
#pragma unroll
    for (int j = 0; j < 4; j++) {
        float v = t[tx][ty + j*8];
        float hi = tf32r(v);
        size_t ix = ((size_t)b*Hh + h0 + ty + j*8)*Nn + n0 + tx;
        g_hsT_hi[ix] = hi;
        g_hsT_lo[ix] = tf32r(v - hi);
    }
}

// ---------------- decoder ----------------
__global__ void k_decoder(const float* __restrict__ Wdec,
                          const float* __restrict__ bdec,
                          float* __restrict__ out) {
    __shared__ float Ws[Hh*Pout + 32];
    int tid = threadIdx.x;
    for (int i = tid; i < Hh*Pout; i += 256) Ws[i] = Wdec[i];
    __syncthreads();
    int row  = blockIdx.x * 8 + (tid >> 5);
    int lane = tid & 31;
    const float* xh = g_h  + (size_t)row * Hh;
    const float* xs = g_hs + (size_t)row * Hh;
    float xr[8];
#pragma unroll
    for (int j = 0; j < 8; j++) xr[j] = xh[lane + j*32] + xs[lane + j*32];
    float acc = 0.f;
    int wl = (lane < Pout) ? lane : 0;
#pragma unroll 4
    for (int k = 0; k < Hh; k++) {
        float xv = __shfl_sync(0xffffffffu, xr[k >> 5], k & 31);
        acc = fmaf(xv, Ws[k*Pout + wl], acc);
    }
    if (lane < Pout)
        out[(size_t)row*Pout + lane] = acc + bdec[lane];
}

// ---------------- launch ----------------
extern "C" void kernel_launch(void* const* d_in, const int* in_sizes, int n_in,
                              void* d_out, int out_size) {
    const float* obs    = (const float*)d_in[0];
    const int*   idx    = (const int*)  d_in[1];
    const float* Wenc   = (const float*)d_in[2];
    const float* benc   = (const float*)d_in[3];
    const float* thetas = (const float*)d_in[4];
    const float* cbias  = (const float*)d_in[5];
    const float* gam    = (const float*)d_in[6];
    const float* bet    = (const float*)d_in[7];
    const float* Wdec   = (const float*)d_in[8];
    const float* bdec   = (const float*)d_in[9];
    float* out = (float*)d_out;

    float *dHc, *dHcT, *dhsTh, *dhsTl, *dYh, *dYl, *dZTh, *dZTl, *dhc, *dthh, *dthl, *dinvb, *dinvd;
    cudaGetSymbolAddress((void**)&dHc,   g_Hc);
    cudaGetSymbolAddress((void**)&dHcT,  g_HcT);
    cudaGetSymbolAddress((void**)&dhsTh, g_hsT_hi);
    cudaGetSymbolAddress((void**)&dhsTl, g_hsT_lo);
    cudaGetSymbolAddress((void**)&dYh,   g_Y_hi);
    cudaGetSymbolAddress((void**)&dYl,   g_Y_lo);
    cudaGetSymbolAddress((void**)&dZTh,  g_ZT_hi);
    cudaGetSymbolAddress((void**)&dZTl,  g_ZT_lo);
    cudaGetSymbolAddress((void**)&dhc,   g_hc);
    cudaGetSymbolAddress((void**)&dthh,  g_thT_hi);
    cudaGetSymbolAddress((void**)&dthl,  g_thT_lo);
    cudaGetSymbolAddress((void**)&dinvb, g_invb);
    cudaGetSymbolAddress((void**)&dinvd, g_invd);

    const int SMEM0 = 6 * TILE_FLOATS * 4;   // SPLITA=0
    const int SMEM1 = 8 * TILE_FLOATS * 4;   // SPLITA=1
    cudaFuncSetAttribute(k_mma2<0>, cudaFuncAttributeMaxDynamicSharedMemorySize, SMEM0);
    cudaFuncSetAttribute(k_mma2<1>, cudaFuncAttributeMaxDynamicSharedMemorySize, SMEM1);

    k_encoder<<<Bn*Nn, Hh>>>(obs, Wenc, benc);
    k_zero_dense<<<Bn*Nn*Mm/256, 256>>>();
    k_zero_small<<<(Bn*Nn + 255)/256, 256>>>();
    k_build<<<Bn*Ee/256, 256>>>(idx);
    k_invdeg<<<(Bn*Nn + 255)/256, 256>>>();
    k_trans_theta<<<dim3(Hh/32, Hh/32, Ll), dim3(32, 8)>>>(thetas);

    for (int l = 0; l < Ll; l++) {
        // S1: Y[b](128x256) = Binv * (HcT[b](128x512) @ hsT[b](256x512)^T), out split
        k_mma2<0><<<dim3(2, 1, Bn), 256, SMEM0>>>(dHcT, nullptr, dhsTh, dhsTl,
            dYh, dYl, dinvb, nullptr, 512, 256, (long)Mm*Nn, (long)Hh*Nn, (long)Mm*Hh);
        // S2: ZT[b](256x128) = thT_l(256x256) @ Y[b](128x256)^T, out split
        k_mma2<1><<<dim3(1, 2, Bn), 256, SMEM1>>>(dthh + (size_t)l*Hh*Hh, dthl + (size_t)l*Hh*Hh,
            dYh, dYl, dZTh, dZTl, nullptr, nullptr, 256, 128, 0L, (long)Mm*Hh, (long)Hh*Mm);
        // S3: hc[b](512x256) = Dinv * (Hc[b](512x128) @ ZT[b](256x128)^T) + bias, fp32 out
        k_mma2<0><<<dim3(2, 4, Bn), 256, SMEM0>>>(dHc, nullptr, dZTh, dZTl,
            dhc, nullptr, dinvd, cbias + (size_t)l*Hh, 128, 256, (long)Nn*Mm, (long)Hh*Mm, (long)Nn*Hh);
        k_zero_stats<<<Bn*Hh/256, 256>>>();
        k_bnstats<<<dim3(Bn, 4), Hh>>>();
        k_bnapply_t<<<dim3(Hh/32, Nn/32, Bn), dim3(32, 8)>>>(gam, bet, l, (int)(l == Ll-1));
    }

    k_decoder<<<Bn*Nn/8, 256>>>(Wdec, bdec, out);
}

// round 6
// speedup vs baseline: 5.9836x; 1.0854x over previous
#include <cuda_runtime.h>
#include <cstdint>

#define Bn   64
#define Nn   512
#define Tt   8
#define DINd 2
#define Hh   256
#define Ll   3
#define Ee   8192
#define Mm   128
#define Pout 24
#define EPSf 1e-5f

// ---------------- scratch (allocation-free) ----------------
__device__ float g_h      [Bn*Nn*Hh];
__device__ float g_hs     [Bn*Nn*Hh];
__device__ float g_hsT_hi [Bn*Hh*Nn];
__device__ float g_hsT_lo [Bn*Hh*Nn];
__device__ float g_hc     [Bn*Nn*Hh];
__device__ float g_Yp0    [Bn*Mm*Hh];   // S1 split-K partial 0
__device__ float g_Yp1    [Bn*Mm*Hh];   // S1 split-K partial 1
__device__ float g_Y_hi   [Bn*Mm*Hh];
__device__ float g_Y_lo   [Bn*Mm*Hh];
__device__ float g_ZT_hi  [Bn*Hh*Mm];
__device__ float g_ZT_lo  [Bn*Hh*Mm];
__device__ float g_Hc     [Bn*Nn*Mm];   // raw integer counts (tf32-exact)
__device__ float g_HcT    [Bn*Mm*Nn];   // raw integer counts (tf32-exact)
__device__ float g_thT_hi [Ll*Hh*Hh];
__device__ float g_thT_lo [Ll*Hh*Hh];
__device__ float g_invb   [Bn*Mm];
__device__ float g_invd   [Bn*Nn];
__device__ int   g_cntm   [Bn*Mm];
__device__ int   g_cntn   [Bn*Nn];
__device__ float g_sum    [Bn*Hh];
__device__ float g_sq     [Bn*Hh];

// ================= helpers =================
__device__ __forceinline__ uint32_t smem_u32(const void* p) {
    uint32_t a;
    asm("{ .reg .u64 t; cvta.to.shared.u64 t, %1; cvt.u32.u64 %0, t; }" : "=r"(a) : "l"(p));
    return a;
}
__device__ __forceinline__ float tf32r(float x) {
    uint32_t u;
    asm("cvt.rna.tf32.f32 %0, %1;" : "=r"(u) : "f"(x));
    return __uint_as_float(u);
}
#define CP16(dst, src) asm volatile("cp.async.cg.shared.global [%0], [%1], 16;" :: "r"(dst), "l"(src) : "memory")
#define CPCOMMIT()     asm volatile("cp.async.commit_group;" ::: "memory")
#define CPWAIT1()      asm volatile("cp.async.wait_group 1;" ::: "memory")

__device__ __forceinline__ void mma_tf32(float* c, const uint32_t* a, const uint32_t* b) {
    asm volatile(
        "mma.sync.aligned.m16n8k8.row.col.f32.tf32.tf32.f32 "
        "{%0,%1,%2,%3}, {%4,%5,%6,%7}, {%8,%9}, {%0,%1,%2,%3};"
        : "+f"(c[0]), "+f"(c[1]), "+f"(c[2]), "+f"(c[3])
        : "r"(a[0]), "r"(a[1]), "r"(a[2]), "r"(a[3]), "r"(b[0]), "r"(b[1]));
}

// ================= error-compensated tf32 mma.sync GEMM =================
// C[128 x 128 tile] = A @ Bhi^T + A @ Blo^T           (SPLITA=0; A exact in tf32)
//                   = Ah@Bh^T + Ah@Bl^T + Al@Bh^T     (SPLITA=1)
// K-major operands. Block 128x128, 4 warps (2x2) of 64x64, BK=32.
// smem: stride-32 with XOR-by-4*(row&7) swizzle, 2-stage cp.async.
// Epilogue: optional rowscale, bias; fp32 out (Cl=0) or tf32 hi/lo split;
// optional fused BN column stats (dostats) via shfl + global atomics.
#define TFL 4096   // floats per tile (128*32)

template<int SPLITA>
__global__ void __launch_bounds__(128)
k_mma2(const float* __restrict__ Ah, const float* __restrict__ Al,
       const float* __restrict__ Bh, const float* __restrict__ Bl,
       float* __restrict__ Cg, float* __restrict__ Clg,
       const float* __restrict__ rowscale, const float* __restrict__ bias,
       int K, int lda, int ldb, int N,
       long sA, long sB, long sC, int dostats) {
    extern __shared__ float sm[];
    uint32_t sbase = smem_u32(sm);
    const int O_AH = 0;
    const int O_AL = SPLITA ? 2 * TFL : 0;
    const int O_BH = (SPLITA ? 4 : 2) * TFL;
    const int O_BL = O_BH + 2 * TFL;

    int tid = threadIdx.x, lane = tid & 31, wid = tid >> 5;
    int wm = wid >> 1, wn = wid & 1;          // 2x2 warp grid, warp tile 64x64
    int row0 = blockIdx.y * 128, col0 = blockIdx.x * 128;
    int z = blockIdx.z;
    const float* pAh = Ah + (size_t)z * sA;
    const float* pAl = SPLITA ? (Al + (size_t)z * sA) : nullptr;
    const float* pBh = Bh + (size_t)z * sB;
    const float* pBl = Bl + (size_t)z * sB;
    float* C  = Cg  + (size_t)z * sC;
    float* Cl = Clg ? (Clg + (size_t)z * sC) : nullptr;

    // cp.async mapping: 128 thr, 8 chunks of 16B per tile
    int cr = tid >> 3;                 // 0..15
    int cc = (tid & 7) * 4;            // 0,4,..,28

    float acc[4][8][4];
#pragma unroll
    for (int i = 0; i < 4; i++)
#pragma unroll
        for (int j = 0; j < 8; j++)
#pragma unroll
            for (int q = 0; q < 4; q++) acc[i][j][q] = 0.f;

    int nkb = K >> 5;

#pragma unroll
    for (int s = 0; s < 2; s++) {
        int kk = s * 32;
#pragma unroll
        for (int i = 0; i < 8; i++) {
            int rr = cr + i * 16;
            uint32_t scol = (uint32_t)(cc ^ ((rr & 7) * 4));
            uint32_t so = (uint32_t)(s * TFL + rr * 32 + scol) * 4;
            size_t ga = (size_t)(row0 + rr) * lda + kk + cc;
            size_t gb = (size_t)(col0 + rr) * ldb + kk + cc;
            CP16(sbase + O_AH * 4 + so, pAh + ga);
            if (SPLITA) CP16(sbase + O_AL * 4 + so, pAl + ga);
            CP16(sbase + O_BH * 4 + so, pBh + gb);
            CP16(sbase + O_BL * 4 + so, pBl + gb);
        }
        CPCOMMIT();
    }

    int g = lane >> 2, t = lane & 3;
    int arow = (wm * 64 + g) * 32;     // float offset of this thread's A row base
    int brow = (wn * 64 + g) * 32;
    int sxor = g * 4;

    for (int kb = 0; kb < nkb; kb++) {
        int s = kb & 1;
        CPWAIT1();
        __syncthreads();

        const float* At  = sm + O_AH + s * TFL;
        const float* Atl = sm + O_AL + s * TFL;
        const float* Bt  = sm + O_BH + s * TFL;
        const float* Btl = sm + O_BL + s * TFL;

#pragma unroll
        for (int ks = 0; ks < 4; ks++) {
            int kc  = ks * 8 + t;
            int xc0 = kc ^ sxor;
            int xc4 = (kc + 4) ^ sxor;
            uint32_t a[4][4], al[4][4], bh[8][2], bl[8][2];
#pragma unroll
            for (int mf = 0; mf < 4; mf++) {
                int o = arow + mf * 512;
                a[mf][0] = __float_as_uint(At[o + xc0]);
                a[mf][1] = __float_as_uint(At[o + 256 + xc0]);
                a[mf][2] = __float_as_uint(At[o + xc4]);
                a[mf][3] = __float_as_uint(At[o + 256 + xc4]);
                if (SPLITA) {
                    al[mf][0] = __float_as_uint(Atl[o + xc0]);
                    al[mf][1] = __float_as_uint(Atl[o + 256 + xc0]);
                    al[mf][2] = __float_as_uint(Atl[o + xc4]);
                    al[mf][3] = __float_as_uint(Atl[o + 256 + xc4]);
                }
            }
#pragma unroll
            for (int nf = 0; nf < 8; nf++) {
                int o = brow + nf * 256;
                bh[nf][0] = __float_as_uint(Bt[o + xc0]);
                bh[nf][1] = __float_as_uint(Bt[o + xc4]);
                bl[nf][0] = __float_as_uint(Btl[o + xc0]);
                bl[nf][1] = __float_as_uint(Btl[o + xc4]);
            }
#pragma unroll
            for (int mf = 0; mf < 4; mf++)
#pragma unroll
                for (int nf = 0; nf < 8; nf++)
                    mma_tf32(acc[mf][nf], a[mf], bh[nf]);
#pragma unroll
            for (int mf = 0; mf < 4; mf++)
#pragma unroll
                for (int nf = 0; nf < 8; nf++)
                    mma_tf32(acc[mf][nf], a[mf], bl[nf]);
            if (SPLITA) {
#pragma unroll
                for (int mf = 0; mf < 4; mf++)
#pragma unroll
                    for (int nf = 0; nf < 8; nf++)
                        mma_tf32(acc[mf][nf], al[mf], bh[nf]);
            }
        }
        __syncthreads();

        if (kb + 2 < nkb) {
            int kk = (kb + 2) * 32;
#pragma unroll
            for (int i = 0; i < 8; i++) {
                int rr = cr + i * 16;
                uint32_t scol = (uint32_t)(cc ^ ((rr & 7) * 4));
                uint32_t so = (uint32_t)(s * TFL + rr * 32 + scol) * 4;
                size_t ga = (size_t)(row0 + rr) * lda + kk + cc;
                size_t gb = (size_t)(col0 + rr) * ldb + kk + cc;
                CP16(sbase + O_AH * 4 + so, pAh + ga);
                if (SPLITA) CP16(sbase + O_AL * 4 + so, pAl + ga);
                CP16(sbase + O_BH * 4 + so, pBh + gb);
                CP16(sbase + O_BL * 4 + so, pBl + gb);
            }
        }
        CPCOMMIT();
    }

    // ---------------- epilogue ----------------
    const float* rsb = rowscale ? rowscale + (size_t)z * (gridDim.y * 128) : nullptr;
    float cs[16], cq[16];
    if (dostats) {
#pragma unroll
        for (int i = 0; i < 16; i++) { cs[i] = 0.f; cq[i] = 0.f; }
    }
#pragma unroll
    for (int mf = 0; mf < 4; mf++) {
        int rr = row0 + wm * 64 + mf * 16 + g;
        float rs0 = rsb ? rsb[rr]     : 1.f;
        float rs1 = rsb ? rsb[rr + 8] : 1.f;
#pragma unroll
        for (int nf = 0; nf < 8; nf++) {
            int ccg = col0 + wn * 64 + nf * 8 + t * 2;
            float c0 = acc[mf][nf][0] * rs0, c1 = acc[mf][nf][1] * rs0;
            float c2 = acc[mf][nf][2] * rs1, c3 = acc[mf][nf][3] * rs1;
            if (bias) {
                float b0 = bias[ccg], b1 = bias[ccg + 1];
                c0 += b0; c1 += b1; c2 += b0; c3 += b1;
            }
            if (dostats) {
                cs[nf*2]   += c0 + c2;  cs[nf*2+1] += c1 + c3;
                cq[nf*2]   += c0*c0 + c2*c2;
                cq[nf*2+1] += c1*c1 + c3*c3;
            }
            if (Cl) {
                float h0 = tf32r(c0), h1 = tf32r(c1), h2 = tf32r(c2), h3 = tf32r(c3);
                *reinterpret_cast<float2*>(&C [(size_t)rr * N + ccg])       = make_float2(h0, h1);
                *reinterpret_cast<float2*>(&C [(size_t)(rr + 8) * N + ccg]) = make_float2(h2, h3);
                *reinterpret_cast<float2*>(&Cl[(size_t)rr * N + ccg])       = make_float2(tf32r(c0 - h0), tf32r(c1 - h1));
                *reinterpret_cast<float2*>(&Cl[(size_t)(rr + 8) * N + ccg]) = make_float2(tf32r(c2 - h2), tf32r(c3 - h3));
            } else {
                *reinterpret_cast<float2*>(&C[(size_t)rr * N + ccg])       = make_float2(c0, c1);
                *reinterpret_cast<float2*>(&C[(size_t)(rr + 8) * N + ccg]) = make_float2(c2, c3);
            }
        }
    }
    if (dostats) {
        // reduce over g (lane bits 2..4), then lanes g==0 publish
#pragma unroll
        for (int off = 4; off <= 16; off <<= 1) {
#pragma unroll
            for (int i = 0; i < 16; i++) {
                cs[i] += __shfl_xor_sync(0xffffffffu, cs[i], off);
                cq[i] += __shfl_xor_sync(0xffffffffu, cq[i], off);
            }
        }
        if (g == 0) {
#pragma unroll
            for (int nf = 0; nf < 8; nf++) {
#pragma unroll
                for (int j = 0; j < 2; j++) {
                    int ccg = col0 + wn * 64 + nf * 8 + t * 2 + j;
                    atomicAdd(&g_sum[z * Hh + ccg], cs[nf*2+j]);
                    atomicAdd(&g_sq [z * Hh + ccg], cq[nf*2+j]);
                }
            }
        }
    }
}

// ---------------- S1 split-K combine: Y = invb * (P0 + P1), hi/lo split ----------------
__global__ void k_combineY() {
    int i = blockIdx.x * 256 + threadIdx.x;       // over Bn*Mm*Hh
    int b   = i >> 15;
    int row = (i >> 8) & (Mm - 1);
    float v = (g_Yp0[i] + g_Yp1[i]) * g_invb[b * Mm + row];
    float hi = tf32r(v);
    g_Y_hi[i] = hi;
    g_Y_lo[i] = tf32r(v - hi);
}

// ---------------- encoder ----------------
__global__ void k_encoder(const float* __restrict__ obs,
                          const float* __restrict__ Wenc,
                          const float* __restrict__ benc) {
    int bn = blockIdx.x;
    int h  = threadIdx.x;
    int b  = bn >> 9, n = bn & (Nn - 1);
    __shared__ float srow[Tt*DINd];
    if (h < Tt*DINd) srow[h] = obs[bn*Tt*DINd + h];
    __syncthreads();
    float w0 = Wenc[h], w1 = Wenc[Hh + h], bb = benc[h];
    float acc = 0.f;
#pragma unroll
    for (int t = 0; t < Tt; t++) {
        float v = fmaf(srow[2*t], w0, fmaf(srow[2*t+1], w1, bb));
        acc += fmaxf(v, 0.f);
    }
    float r = acc * (1.f / Tt);
    g_h[(size_t)bn*Hh + h] = r;
    float hi = tf32r(r);
    size_t ix = ((size_t)b*Hh + h)*Nn + n;
    g_hsT_hi[ix] = hi;
    g_hsT_lo[ix] = tf32r(r - hi);
}

// ---------------- incidence build (raw counts) ----------------
__global__ void k_zero_dense() {
    int i = blockIdx.x * blockDim.x + threadIdx.x;
    g_Hc[i]  = 0.f;
    g_HcT[i] = 0.f;
}
__global__ void k_zero_small() {
    int i = blockIdx.x * blockDim.x + threadIdx.x;
    if (i < Bn*Mm) g_cntm[i] = 0;
    if (i < Bn*Nn) g_cntn[i] = 0;
}
__global__ void k_build(const int* __restrict__ idx) {
    int i = blockIdx.x * blockDim.x + threadIdx.x;
    int b = i >> 13, e = i & (Ee - 1);
    int n = idx[b*2*Ee + e];
    int m = idx[b*2*Ee + Ee + e];
    atomicAdd(&g_Hc [((size_t)b*Nn + n)*Mm + m], 1.f);
    atomicAdd(&g_HcT[((size_t)b*Mm + m)*Nn + n], 1.f);
    atomicAdd(&g_cntn[b*Nn + n], 1);
    atomicAdd(&g_cntm[b*Mm + m], 1);
}
__global__ void k_invdeg() {
    int i = blockIdx.x * blockDim.x + threadIdx.x;
    if (i < Bn*Mm) g_invb[i] = 1.f / fmaxf((float)g_cntm[i], 1.f);
    if (i < Bn*Nn) g_invd[i] = 1.f / fmaxf((float)g_cntn[i], 1.f);
}

// ---------------- theta transpose (split) ----------------
__global__ void k_trans_theta(const float* __restrict__ thetas) {
    __shared__ float t[32][33];
    int l  = blockIdx.z;
    int x0 = blockIdx.x * 32, y0 = blockIdx.y * 32;
    int tx = threadIdx.x, ty = threadIdx.y;
    const float* src = thetas + (size_t)l * Hh * Hh;
#pragma unroll
    for (int j = 0; j < 4; j++)
        t[ty + j*8][tx] = src[(size_t)(y0 + ty + j*8)*Hh + x0 + tx];
    __syncthreads();
#pragma unroll
    for (int j = 0; j < 4; j++) {
        float v = t[tx][ty + j*8];
        float hi = tf32r(v);
        size_t ix = (size_t)l*Hh*Hh + (size_t)(x0 + ty + j*8)*Hh + y0 + tx;
        g_thT_hi[ix] = hi;
        g_thT_lo[ix] = tf32r(v - hi);
    }
}

__global__ void k_zero_stats() {
    int i = blockIdx.x * blockDim.x + threadIdx.x;
    g_sum[i] = 0.f;
    g_sq[i]  = 0.f;
}

// ---------------- BN apply + relu -> hsT split (+ hs row-major last layer) ----------------
__global__ void k_bnapply_t(const float* __restrict__ gam,
                            const float* __restrict__ bet, int l, int writeRow) {
    __shared__ float t[32][33];
    int b  = blockIdx.z;
    int h0 = blockIdx.x * 32, n0 = blockIdx.y * 32;
    int tx = threadIdx.x, ty = threadIdx.y;
    int h  = h0 + tx;
    float mean = g_sum[b*Hh + h] * (1.f / Nn);
    float var  = g_sq [b*Hh + h] * (1.f / Nn) - mean*mean;
    float rstd = rsqrtf(var + EPSf);
    float gm = gam[l*Hh + h], bt = bet[l*Hh + h];
#pragma unroll
    for (int j = 0; j < 4; j++) {
        int n = n0 + ty + j*8;
        size_t ix = ((size_t)b*Nn + n)*Hh + h;
        float v = fmaxf((g_hc[ix] - mean) * rstd * gm + bt, 0.f);
        if (writeRow) g_hs[ix] = v;
        t[ty + j*8][tx] = v;
    }
    __syncthreads();
#pragma unroll
    for (int j = 0; j < 4; j++) {
        float v = t[tx][ty + j*8];
        float hi = tf32r(v);
        size_t ix = ((size_t)b*Hh + h0 + ty + j*8)*Nn + n0 + tx;
        g_hsT_hi[ix] = hi;
        g_hsT_lo[ix] = tf32r(v - hi);
    }
}

// ---------------- decoder ----------------
__global__ void k_decoder(const float* __restrict__ Wdec,
                          const float* __restrict__ bdec,
                          float* __restrict__ out) {
    __shared__ float Ws[Hh*Pout + 32];
    int tid = threadIdx.x;
    for (int i = tid; i < Hh*Pout; i += 256) Ws[i] = Wdec[i];
    __syncthreads();
    int row  = blockIdx.x * 8 + (tid >> 5);
    int lane = tid & 31;
    const float* xh = g_h  + (size_t)row * Hh;
    const float* xs = g_hs + (size_t)row * Hh;
    float xr[8];
#pragma unroll
    for (int j = 0; j < 8; j++) xr[j] = xh[lane + j*32] + xs[lane + j*32];
    float acc = 0.f;
    int wl = (lane < Pout) ? lane : 0;
#pragma unroll 4
    for (int k = 0; k < Hh; k++) {
        float xv = __shfl_sync(0xffffffffu, xr[k >> 5], k & 31);
        acc = fmaf(xv, Ws[k*Pout + wl], acc);
    }
    if (lane < Pout)
        out[(size_t)row*Pout + lane] = acc + bdec[lane];
}

// ---------------- launch ----------------
extern "C" void kernel_launch(void* const* d_in, const int* in_sizes, int n_in,
                              void* d_out, int out_size) {
    const float* obs    = (const float*)d_in[0];
    const int*   idx    = (const int*)  d_in[1];
    const float* Wenc   = (const float*)d_in[2];
    const float* benc   = (const float*)d_in[3];
    const float* thetas = (const float*)d_in[4];
    const float* cbias  = (const float*)d_in[5];
    const float* gam    = (const float*)d_in[6];
    const float* bet    = (const float*)d_in[7];
    const float* Wdec   = (const float*)d_in[8];
    const float* bdec   = (const float*)d_in[9];
    float* out = (float*)d_out;

    float *dHc, *dHcT, *dhsTh, *dhsTl, *dYp0, *dYp1, *dYh, *dYl, *dZTh, *dZTl;
    float *dhc, *dthh, *dthl, *dinvb, *dinvd;
    cudaGetSymbolAddress((void**)&dHc,   g_Hc);
    cudaGetSymbolAddress((void**)&dHcT,  g_HcT);
    cudaGetSymbolAddress((void**)&dhsTh, g_hsT_hi);
    cudaGetSymbolAddress((void**)&dhsTl, g_hsT_lo);
    cudaGetSymbolAddress((void**)&dYp0,  g_Yp0);
    cudaGetSymbolAddress((void**)&dYp1,  g_Yp1);
    cudaGetSymbolAddress((void**)&dYh,   g_Y_hi);
    cudaGetSymbolAddress((void**)&dYl,   g_Y_lo);
    cudaGetSymbolAddress((void**)&dZTh,  g_ZT_hi);
    cudaGetSymbolAddress((void**)&dZTl,  g_ZT_lo);
    cudaGetSymbolAddress((void**)&dhc,   g_hc);
    cudaGetSymbolAddress((void**)&dthh,  g_thT_hi);
    cudaGetSymbolAddress((void**)&dthl,  g_thT_lo);
    cudaGetSymbolAddress((void**)&dinvb, g_invb);
    cudaGetSymbolAddress((void**)&dinvd, g_invd);

    const int SMEM0 = 6 * TFL * 4;   // 98304
    const int SMEM1 = 8 * TFL * 4;   // 131072
    cudaFuncSetAttribute(k_mma2<0>, cudaFuncAttributeMaxDynamicSharedMemorySize, SMEM0);
    cudaFuncSetAttribute(k_mma2<1>, cudaFuncAttributeMaxDynamicSharedMemorySize, SMEM1);

    k_encoder<<<Bn*Nn, Hh>>>(obs, Wenc, benc);
    k_zero_dense<<<Bn*Nn*Mm/256, 256>>>();
    k_zero_small<<<(Bn*Nn + 255)/256, 256>>>();
    k_build<<<Bn*Ee/256, 256>>>(idx);
    k_invdeg<<<(Bn*Nn + 255)/256, 256>>>();
    k_trans_theta<<<dim3(Hh/32, Hh/32, Ll), dim3(32, 8)>>>(thetas);

    for (int l = 0; l < Ll; l++) {
        k_zero_stats<<<Bn*Hh/256, 256>>>();
        // S1 split-K: Yp = HcT[b](128x512) @ hsT[b](256x512)^T  (two K halves)
        k_mma2<0><<<dim3(2, 1, Bn), 128, SMEM0>>>(dHcT, nullptr, dhsTh, dhsTl,
            dYp0, nullptr, nullptr, nullptr, 256, Nn, Nn, Hh,
            (long)Mm*Nn, (long)Hh*Nn, (long)Mm*Hh, 0);
        k_mma2<0><<<dim3(2, 1, Bn), 128, SMEM0>>>(dHcT + 256, nullptr, dhsTh + 256, dhsTl + 256,
            dYp1, nullptr, nullptr, nullptr, 256, Nn, Nn, Hh,
            (long)Mm*Nn, (long)Hh*Nn, (long)Mm*Hh, 0);
        k_combineY<<<Bn*Mm*Hh/256, 256>>>();
        // S2: ZT[b](256x128) = thT_l(256x256) @ Y[b](128x256)^T, split out
        k_mma2<1><<<dim3(1, 2, Bn), 128, SMEM1>>>(dthh + (size_t)l*Hh*Hh, dthl + (size_t)l*Hh*Hh,
            dYh, dYl, dZTh, dZTl, nullptr, nullptr, 256, Hh, Hh, Mm,
            0L, (long)Mm*Hh, (long)Hh*Mm, 0);
        // S3: hc[b](512x256) = Dinv*(Hc[b](512x128) @ ZT[b](256x128)^T) + bias, fused BN stats
        k_mma2<0><<<dim3(2, 4, Bn), 128, SMEM0>>>(dHc, nullptr, dZTh, dZTl,
            dhc, nullptr, dinvd, cbias + (size_t)l*Hh, 128, Mm, Mm, Hh,
            (long)Nn*Mm, (long)Hh*Mm, (long)Nn*Hh, 1);
        k_bnapply_t<<<dim3(Hh/32, Nn/32, Bn), dim3(32, 8)>>>(gam, bet, l, (int)(l == Ll-1));
    }

    k_decoder<<<Bn*Nn/8, 256>>>(Wdec, bdec, out);
}

// round 7
// speedup vs baseline: 6.2870x; 1.0507x over previous
#include <cuda_runtime.h>
#include <cstdint>

#define Bn   64
#define Nn   512
#define Tt   8
#define DINd 2
#define Hh   256
#define Ll   3
#define Ee   8192
#define Mm   128
#define Pout 24
#define EPSf 1e-5f

// ---------------- scratch (allocation-free) ----------------
__device__ float g_h      [Bn*Nn*Hh];
__device__ float g_hs     [Bn*Nn*Hh];
__device__ float g_hsT_hi [Bn*Hh*Nn];
__device__ float g_hsT_lo [Bn*Hh*Nn];
__device__ float g_hc     [Bn*Nn*Hh];
__device__ float g_Yp     [2*Bn*Mm*Hh];  // S1 split-K partials
__device__ float g_Y_hi   [Bn*Mm*Hh];
__device__ float g_Y_lo   [Bn*Mm*Hh];
__device__ float g_ZT_hi  [Bn*Hh*Mm];
__device__ float g_ZT_lo  [Bn*Hh*Mm];
__device__ float g_Hc     [Bn*Nn*Mm];    // raw integer counts (tf32-exact)
__device__ float g_HcT    [Bn*Mm*Nn];    // raw integer counts (tf32-exact)
__device__ float g_thT_hi [Ll*Hh*Hh];
__device__ float g_thT_lo [Ll*Hh*Hh];
__device__ float g_invb   [Bn*Mm];
__device__ float g_invd   [Bn*Nn];
__device__ int   g_cntm   [Bn*Mm];
__device__ int   g_cntn   [Bn*Nn];
__device__ float g_sum    [Bn*Hh];
__device__ float g_sq     [Bn*Hh];

// ================= helpers =================
__device__ __forceinline__ uint32_t smem_u32(const void* p) {
    uint32_t a;
    asm("{ .reg .u64 t; cvta.to.shared.u64 t, %1; cvt.u32.u64 %0, t; }" : "=r"(a) : "l"(p));
    return a;
}
__device__ __forceinline__ float tf32r(float x) {
    uint32_t u;
    asm("cvt.rna.tf32.f32 %0, %1;" : "=r"(u) : "f"(x));
    return __uint_as_float(u);
}
#define CP16(dst, src) asm volatile("cp.async.cg.shared.global [%0], [%1], 16;" :: "r"(dst), "l"(src) : "memory")
#define CPCOMMIT()     asm volatile("cp.async.commit_group;" ::: "memory")
#define CPWAIT1()      asm volatile("cp.async.wait_group 1;" ::: "memory")

__device__ __forceinline__ void mma_tf32(float* c, const uint32_t* a, const uint32_t* b) {
    asm volatile(
        "mma.sync.aligned.m16n8k8.row.col.f32.tf32.tf32.f32 "
        "{%0,%1,%2,%3}, {%4,%5,%6,%7}, {%8,%9}, {%0,%1,%2,%3};"
        : "+f"(c[0]), "+f"(c[1]), "+f"(c[2]), "+f"(c[3])
        : "r"(a[0]), "r"(a[1]), "r"(a[2]), "r"(a[3]), "r"(b[0]), "r"(b[1]));
}

// ================= error-compensated tf32 mma.sync GEMM =================
// Block tile 128x64 (M x N), BK=32, 4 warps (2x2), warp tile 64x32.
// SPLITA=0: C = A@Bhi^T + A@Blo^T        (A exact in tf32)
// SPLITA=1: C = Ah@Bh^T + Ah@Bl^T + Al@Bh^T
// K-major operands, stride-32 smem with XOR-by-4*(row&7) swizzle, 2-stage cp.async.
// If koffY != 0: blockIdx.y selects a K-slice (k_base = y*koffY) and an output
// partial buffer (C += y*cOffY), with row0 = 0 (split-K). Else row0 = y*128.
// Epilogue: optional rowscale, bias; fp32 out (Cl=0) or tf32 hi/lo split;
// optional fused BN column stats (dostats) via shfl + global atomics.
#define AFL 4096   // A tile floats (128*32)
#define BFL 2048   // B tile floats (64*32)

template<int SPLITA>
__global__ void __launch_bounds__(128)
k_mma2(const float* __restrict__ Ah, const float* __restrict__ Al,
       const float* __restrict__ Bh, const float* __restrict__ Bl,
       float* __restrict__ Cg, float* __restrict__ Clg,
       const float* __restrict__ rowscale, const float* __restrict__ bias,
       int K, int lda, int ldb, int N, int M,
       long sA, long sB, long sC, int dostats,
       int koffY, long cOffY) {
    extern __shared__ float sm[];
    uint32_t sbase = smem_u32(sm);
    const int O_AH = 0;
    const int O_AL = 8192;                        // only used if SPLITA
    const int O_BH = SPLITA ? 16384 : 8192;
    const int O_BL = O_BH + 2 * BFL;

    int tid = threadIdx.x, lane = tid & 31, wid = tid >> 5;
    int wm = wid >> 1, wn = wid & 1;              // 2x2 warps
    int col0 = blockIdx.x * 64;
    int row0, k_base;
    long cadd;
    if (koffY) { row0 = 0; k_base = blockIdx.y * koffY; cadd = (long)blockIdx.y * cOffY; }
    else       { row0 = blockIdx.y * 128; k_base = 0; cadd = 0; }
    int z = blockIdx.z;
    const float* pAh = Ah + (size_t)z * sA + k_base;
    const float* pAl = SPLITA ? (Al + (size_t)z * sA + k_base) : nullptr;
    const float* pBh = Bh + (size_t)z * sB + k_base;
    const float* pBl = Bl + (size_t)z * sB + k_base;
    float* C  = Cg + (size_t)z * sC + cadd;
    float* Cl = Clg ? (Clg + (size_t)z * sC) : nullptr;

    int cr = tid >> 3;                 // 0..15
    int cc = (tid & 7) * 4;

    float acc[4][4][4];
#pragma unroll
    for (int i = 0; i < 4; i++)
#pragma unroll
        for (int j = 0; j < 4; j++)
#pragma unroll
            for (int q = 0; q < 4; q++) acc[i][j][q] = 0.f;

    int nkb = K >> 5;

#pragma unroll
    for (int s = 0; s < 2; s++) {
        int kk = s * 32;
#pragma unroll
        for (int i = 0; i < 8; i++) {             // A: 128 rows
            int rr = cr + i * 16;
            uint32_t so = (uint32_t)(O_AH + s * AFL + rr * 32 + (cc ^ ((rr & 7) * 4))) * 4;
            CP16(sbase + so, pAh + (size_t)(row0 + rr) * lda + kk + cc);
            if (SPLITA) CP16(sbase + (uint32_t)(O_AL - O_AH) * 4 + so,
                             pAl + (size_t)(row0 + rr) * lda + kk + cc);
        }
#pragma unroll
        for (int i = 0; i < 4; i++) {             // B: 64 rows
            int rr = cr + i * 16;
            uint32_t sw = (uint32_t)(rr * 32 + (cc ^ ((rr & 7) * 4)));
            size_t gb = (size_t)(col0 + rr) * ldb + kk + cc;
            CP16(sbase + (uint32_t)(O_BH + s * BFL + sw) * 4, pBh + gb);
            CP16(sbase + (uint32_t)(O_BL + s * BFL + sw) * 4, pBl + gb);
        }
        CPCOMMIT();
    }

    int g = lane >> 2, t = lane & 3;
    int arow = (wm * 64 + g) * 32;
    int brow = (wn * 32 + g) * 32;
    int sxor = g * 4;

    for (int kb = 0; kb < nkb; kb++) {
        int s = kb & 1;
        CPWAIT1();
        __syncthreads();

        const float* At  = sm + O_AH + s * AFL;
        const float* Atl = sm + O_AL + s * AFL;
        const float* Bt  = sm + O_BH + s * BFL;
        const float* Btl = sm + O_BL + s * BFL;

#pragma unroll
        for (int ks = 0; ks < 4; ks++) {
            int kc  = ks * 8 + t;
            int xc0 = kc ^ sxor;
            int xc4 = (kc + 4) ^ sxor;
            uint32_t a[4][4], al[4][4], bh[4][2], bl[4][2];
#pragma unroll
            for (int mf = 0; mf < 4; mf++) {
                int o = arow + mf * 512;
                a[mf][0] = __float_as_uint(At[o + xc0]);
                a[mf][1] = __float_as_uint(At[o + 256 + xc0]);
                a[mf][2] = __float_as_uint(At[o + xc4]);
                a[mf][3] = __float_as_uint(At[o + 256 + xc4]);
                if (SPLITA) {
                    al[mf][0] = __float_as_uint(Atl[o + xc0]);
                    al[mf][1] = __float_as_uint(Atl[o + 256 + xc0]);
                    al[mf][2] = __float_as_uint(Atl[o + xc4]);
                    al[mf][3] = __float_as_uint(Atl[o + 256 + xc4]);
                }
            }
#pragma unroll
            for (int nf = 0; nf < 4; nf++) {
                int o = brow + nf * 256;
                bh[nf][0] = __float_as_uint(Bt[o + xc0]);
                bh[nf][1] = __float_as_uint(Bt[o + xc4]);
                bl[nf][0] = __float_as_uint(Btl[o + xc0]);
                bl[nf][1] = __float_as_uint(Btl[o + xc4]);
            }
#pragma unroll
            for (int mf = 0; mf < 4; mf++)
#pragma unroll
                for (int nf = 0; nf < 4; nf++)
                    mma_tf32(acc[mf][nf], a[mf], bh[nf]);
#pragma unroll
            for (int mf = 0; mf < 4; mf++)
#pragma unroll
                for (int nf = 0; nf < 4; nf++)
                    mma_tf32(acc[mf][nf], a[mf], bl[nf]);
            if (SPLITA) {
#pragma unroll
                for (int mf = 0; mf < 4; mf++)
#pragma unroll
                    for (int nf = 0; nf < 4; nf++)
                        mma_tf32(acc[mf][nf], al[mf], bh[nf]);
            }
        }
        __syncthreads();

        if (kb + 2 < nkb) {
            int kk = (kb + 2) * 32;
#pragma unroll
            for (int i = 0; i < 8; i++) {
                int rr = cr + i * 16;
                uint32_t so = (uint32_t)(O_AH + s * AFL + rr * 32 + (cc ^ ((rr & 7) * 4))) * 4;
                CP16(sbase + so, pAh + (size_t)(row0 + rr) * lda + kk + cc);
                if (SPLITA) CP16(sbase + (uint32_t)(O_AL - O_AH) * 4 + so,
                                 pAl + (size_t)(row0 + rr) * lda + kk + cc);
            }
#pragma unroll
            for (int i = 0; i < 4; i++) {
                int rr = cr + i * 16;
                uint32_t sw = (uint32_t)(rr * 32 + (cc ^ ((rr & 7) * 4)));
                size_t gb = (size_t)(col0 + rr) * ldb + kk + cc;
                CP16(sbase + (uint32_t)(O_BH + s * BFL + sw) * 4, pBh + gb);
                CP16(sbase + (uint32_t)(O_BL + s * BFL + sw) * 4, pBl + gb);
            }
        }
        CPCOMMIT();
    }

    // ---------------- epilogue ----------------
    const float* rsb = rowscale ? rowscale + (size_t)z * M : nullptr;
    float cs[8], cq[8];
    if (dostats) {
#pragma unroll
        for (int i = 0; i < 8; i++) { cs[i] = 0.f; cq[i] = 0.f; }
    }
#pragma unroll
    for (int mf = 0; mf < 4; mf++) {
        int rr = row0 + wm * 64 + mf * 16 + g;
        float rs0 = rsb ? rsb[rr]     : 1.f;
        float rs1 = rsb ? rsb[rr + 8] : 1.f;
#pragma unroll
        for (int nf = 0; nf < 4; nf++) {
            int ccg = col0 + wn * 32 + nf * 8 + t * 2;
            float c0 = acc[mf][nf][0] * rs0, c1 = acc[mf][nf][1] * rs0;
            float c2 = acc[mf][nf][2] * rs1, c3 = acc[mf][nf][3] * rs1;
            if (bias) {
                float b0 = bias[ccg], b1 = bias[ccg + 1];
                c0 += b0; c1 += b1; c2 += b0; c3 += b1;
            }
            if (dostats) {
                cs[nf*2]   += c0 + c2;  cs[nf*2+1] += c1 + c3;
                cq[nf*2]   += c0*c0 + c2*c2;
                cq[nf*2+1] += c1*c1 + c3*c3;
            }
            if (Cl) {
                float h0 = tf32r(c0), h1 = tf32r(c1), h2 = tf32r(c2), h3 = tf32r(c3);
                *reinterpret_cast<float2*>(&C [(size_t)rr * N + ccg])       = make_float2(h0, h1);
                *reinterpret_cast<float2*>(&C [(size_t)(rr + 8) * N + ccg]) = make_float2(h2, h3);
                *reinterpret_cast<float2*>(&Cl[(size_t)rr * N + ccg])       = make_float2(tf32r(c0 - h0), tf32r(c1 - h1));
                *reinterpret_cast<float2*>(&Cl[(size_t)(rr + 8) * N + ccg]) = make_float2(tf32r(c2 - h2), tf32r(c3 - h3));
            } else {
                *reinterpret_cast<float2*>(&C[(size_t)rr * N + ccg])       = make_float2(c0, c1);
                *reinterpret_cast<float2*>(&C[(size_t)(rr + 8) * N + ccg]) = make_float2(c2, c3);
            }
        }
    }
    if (dostats) {
#pragma unroll
        for (int off = 4; off <= 16; off <<= 1) {
#pragma unroll
            for (int i = 0; i < 8; i++) {
                cs[i] += __shfl_xor_sync(0xffffffffu, cs[i], off);
                cq[i] += __shfl_xor_sync(0xffffffffu, cq[i], off);
            }
        }
        if (g == 0) {
#pragma unroll
            for (int nf = 0; nf < 4; nf++) {
#pragma unroll
                for (int j = 0; j < 2; j++) {
                    int ccg = col0 + wn * 32 + nf * 8 + t * 2 + j;
                    atomicAdd(&g_sum[z * Hh + ccg], cs[nf*2+j]);
                    atomicAdd(&g_sq [z * Hh + ccg], cq[nf*2+j]);
                }
            }
        }
    }
}

// ---------------- S1 split-K combine: Y = invb * (P0 + P1), hi/lo split ----------------
__global__ void k_combineY() {
    int i = blockIdx.x * 256 + threadIdx.x;
    int b   = i >> 15;
    int row = (i >> 8) & (Mm - 1);
    float v = (g_Yp[i] + g_Yp[i + Bn*Mm*Hh]) * g_invb[b * Mm + row];
    float hi = tf32r(v);
    g_Y_hi[i] = hi;
    g_Y_lo[i] = tf32r(v - hi);
}

// ---------------- encoder ----------------
__global__ void k_encoder(const float* __restrict__ obs,
                          const float* __restrict__ Wenc,
                          const float* __restrict__ benc) {
    int bn = blockIdx.x;
    int h  = threadIdx.x;
    int b  = bn >> 9, n = bn & (Nn - 1);
    __shared__ float srow[Tt*DINd];
    if (h < Tt*DINd) srow[h] = obs[bn*Tt*DINd + h];
    __syncthreads();
    float w0 = Wenc[h], w1 = Wenc[Hh + h], bb = benc[h];
    float acc = 0.f;
#pragma unroll
    for (int t = 0; t < Tt; t++) {
        float v = fmaf(srow[2*t], w0, fmaf(srow[2*t+1], w1, bb));
        acc += fmaxf(v, 0.f);
    }
    float r = acc * (1.f / Tt);
    g_h[(size_t)bn*Hh + h] = r;
    float hi = tf32r(r);
    size_t ix = ((size_t)b*Hh + h)*Nn + n;
    g_hsT_hi[ix] = hi;
    g_hsT_lo[ix] = tf32r(r - hi);
}

// ---------------- incidence build (raw counts) ----------------
__global__ void k_zero_dense() {
    int i = blockIdx.x * blockDim.x + threadIdx.x;
    g_Hc[i]  = 0.f;
    g_HcT[i] = 0.f;
    if (i < Bn*Mm) g_cntm[i] = 0;
    if (i < Bn*Nn) g_cntn[i] = 0;
}
__global__ void k_build(const int* __restrict__ idx) {
    int i = blockIdx.x * blockDim.x + threadIdx.x;
    int b = i >> 13, e = i & (Ee - 1);
    int n = idx[b*2*Ee + e];
    int m = idx[b*2*Ee + Ee + e];
    atomicAdd(&g_Hc [((size_t)b*Nn + n)*Mm + m], 1.f);
    atomicAdd(&g_HcT[((size_t)b*Mm + m)*Nn + n], 1.f);
    atomicAdd(&g_cntn[b*Nn + n], 1);
    atomicAdd(&g_cntm[b*Mm + m], 1);
}
__global__ void k_invdeg() {
    int i = blockIdx.x * blockDim.x + threadIdx.x;
    if (i < Bn*Mm) g_invb[i] = 1.f / fmaxf((float)g_cntm[i], 1.f);
    if (i < Bn*Nn) g_invd[i] = 1.f / fmaxf((float)g_cntn[i], 1.f);
}

// ---------------- theta transpose (split) ----------------
__global__ void k_trans_theta(const float* __restrict__ thetas) {
    __shared__ float t[32][33];
    int l  = blockIdx.z;
    int x0 = blockIdx.x * 32, y0 = blockIdx.y * 32;
    int tx = threadIdx.x, ty = threadIdx.y;
    const float* src = thetas + (size_t)l * Hh * Hh;
#pragma unroll
    for (int j = 0; j < 4; j++)
        t[ty + j*8][tx] = src[(size_t)(y0 + ty + j*8)*Hh + x0 + tx];
    __syncthreads();
#pragma unroll
    for (int j = 0; j < 4; j++) {
        float v = t[tx][ty + j*8];
        float hi = tf32r(v);
        size_t ix = (size_t)l*Hh*Hh + (size_t)(x0 + ty + j*8)*Hh + y0 + tx;
        g_thT_hi[ix] = hi;
        g_thT_lo[ix] = tf32r(v - hi);
    }
}

__global__ void k_zero_stats() {
    int i = blockIdx.x * blockDim.x + threadIdx.x;
    g_sum[i] = 0.f;
    g_sq[i]  = 0.f;
}

// ---------------- BN apply + relu -> hsT split (+ hs row-major last layer) ----------------
__global__ void k_bnapply_t(const float* __restrict__ gam,
                            const float* __restrict__ bet, int l, int writeRow) {
    __shared__ float t[32][33];
    int b  = blockIdx.z;
    int h0 = blockIdx.x * 32, n0 = blockIdx.y * 32;
    int tx = threadIdx.x, ty = threadIdx.y;
    int h  = h0 + tx;
    float mean = g_sum[b*Hh + h] * (1.f / Nn);
    float var  = g_sq [b*Hh + h] * (1.f / Nn) - mean*mean;
    float rstd = rsqrtf(var + EPSf);
    float gm = gam[l*Hh + h], bt = bet[l*Hh + h];
#pragma unroll
    for (int j = 0; j < 4; j++) {
        int n = n0 + ty + j*8;
        size_t ix = ((size_t)b*Nn + n)*Hh + h;
        float v = fmaxf((g_hc[ix] - mean) * rstd * gm + bt, 0.f);
        if (writeRow) g_hs[ix] = v;
        t[ty + j*8][tx] = v;
    }
    __syncthreads();
#pragma unroll
    for (int j = 0; j < 4; j++) {
        float v = t[tx][ty + j*8];
        float hi = tf32r(v);
        size_t ix = ((size_t)b*Hh + h0 + ty + j*8)*Nn + n0 + tx;
        g_hsT_hi[ix] = hi;
        g_hsT_lo[ix] = tf32r(v - hi);
    }
}

// ---------------- decoder ----------------
__global__ void k_decoder(const float* __restrict__ Wdec,
                          const float* __restrict__ bdec,
                          float* __restrict__ out) {
    __shared__ float Ws[Hh*Pout + 32];
    int tid = threadIdx.x;
    for (int i = tid; i < Hh*Pout; i += 256) Ws[i] = Wdec[i];
    __syncthreads();
    int row  = blockIdx.x * 8 + (tid >> 5);
    int lane = tid & 31;
    const float* xh = g_h  + (size_t)row * Hh;
    const float* xs = g_hs + (size_t)row * Hh;
    float xr[8];
#pragma unroll
    for (int j = 0; j < 8; j++) xr[j] = xh[lane + j*32] + xs[lane + j*32];
    float acc = 0.f;
    int wl = (lane < Pout) ? lane : 0;
#pragma unroll 4
    for (int k = 0; k < Hh; k++) {
        float xv = __shfl_sync(0xffffffffu, xr[k >> 5], k & 31);
        acc = fmaf(xv, Ws[k*Pout + wl], acc);
    }
    if (lane < Pout)
        out[(size_t)row*Pout + lane] = acc + bdec[lane];
}

// ---------------- launch ----------------
extern "C" void kernel_launch(void* const* d_in, const int* in_sizes, int n_in,
                              void* d_out, int out_size) {
    const float* obs    = (const float*)d_in[0];
    const int*   idx    = (const int*)  d_in[1];
    const float* Wenc   = (const float*)d_in[2];
    const float* benc   = (const float*)d_in[3];
    const float* thetas = (const float*)d_in[4];
    const float* cbias  = (const float*)d_in[5];
    const float* gam    = (const float*)d_in[6];
    const float* bet    = (const float*)d_in[7];
    const float* Wdec   = (const float*)d_in[8];
    const float* bdec   = (const float*)d_in[9];
    float* out = (float*)d_out;

    float *dHc, *dHcT, *dhsTh, *dhsTl, *dYp, *dYh, *dYl, *dZTh, *dZTl;
    float *dhc, *dthh, *dthl, *dinvb, *dinvd;
    cudaGetSymbolAddress((void**)&dHc,   g_Hc);
    cudaGetSymbolAddress((void**)&dHcT,  g_HcT);
    cudaGetSymbolAddress((void**)&dhsTh, g_hsT_hi);
    cudaGetSymbolAddress((void**)&dhsTl, g_hsT_lo);
    cudaGetSymbolAddress((void**)&dYp,   g_Yp);
    cudaGetSymbolAddress((void**)&dYh,   g_Y_hi);
    cudaGetSymbolAddress((void**)&dYl,   g_Y_lo);
    cudaGetSymbolAddress((void**)&dZTh,  g_ZT_hi);
    cudaGetSymbolAddress((void**)&dZTl,  g_ZT_lo);
    cudaGetSymbolAddress((void**)&dhc,   g_hc);
    cudaGetSymbolAddress((void**)&dthh,  g_thT_hi);
    cudaGetSymbolAddress((void**)&dthl,  g_thT_lo);
    cudaGetSymbolAddress((void**)&dinvb, g_invb);
    cudaGetSymbolAddress((void**)&dinvd, g_invd);

    const int SMEM0 = 16384 * 4;   // 64KB  (A hi 2st + B hi/lo 2st)
    const int SMEM1 = 24576 * 4;   // 96KB  (+ A lo 2st)
    cudaFuncSetAttribute(k_mma2<0>, cudaFuncAttributeMaxDynamicSharedMemorySize, SMEM0);
    cudaFuncSetAttribute(k_mma2<1>, cudaFuncAttributeMaxDynamicSharedMemorySize, SMEM1);

    // launch order puts S1 (the GEMM) at position #4 for the profiler
    k_encoder<<<Bn*Nn, Hh>>>(obs, Wenc, benc);                     // 1
    k_zero_dense<<<Bn*Nn*Mm/256, 256>>>();                         // 2
    k_build<<<Bn*Ee/256, 256>>>(idx);                              // 3

    for (int l = 0; l < Ll; l++) {
        // S1 split-K merged launch: Yp[y] = HcT[:,y*256:+256] @ hsT[:,y*256:+256]^T
        k_mma2<0><<<dim3(4, 2, Bn), 128, SMEM0>>>(dHcT, nullptr, dhsTh, dhsTl,
            dYp, nullptr, nullptr, nullptr, 256, Nn, Nn, Hh, Mm,
            (long)Mm*Nn, (long)Hh*Nn, (long)Mm*Hh, 0, 256, (long)Bn*Mm*Hh);   // 4 on l==0
        if (l == 0) {
            k_invdeg<<<(Bn*Nn + 255)/256, 256>>>();
            k_trans_theta<<<dim3(Hh/32, Hh/32, Ll), dim3(32, 8)>>>(thetas);
        }
        k_zero_stats<<<Bn*Hh/256, 256>>>();
        k_combineY<<<Bn*Mm*Hh/256, 256>>>();
        // S2: ZT[b](256x128) = thT_l(256x256) @ Y[b](128x256)^T, split out
        k_mma2<1><<<dim3(2, 2, Bn), 128, SMEM1>>>(dthh + (size_t)l*Hh*Hh, dthl + (size_t)l*Hh*Hh,
            dYh, dYl, dZTh, dZTl, nullptr, nullptr, 256, Hh, Hh, Mm, Hh,
            0L, (long)Mm*Hh, (long)Hh*Mm, 0, 0, 0L);
        // S3: hc[b](512x256) = Dinv*(Hc[b](512x128) @ ZT[b](256x128)^T) + bias, fused BN stats
        k_mma2<0><<<dim3(4, 4, Bn), 128, SMEM0>>>(dHc, nullptr, dZTh, dZTl,
            dhc, nullptr, dinvd, cbias + (size_t)l*Hh, 128, Mm, Mm, Hh, Nn,
            (long)Nn*Mm, (long)Hh*Mm, (long)Nn*Hh, 1, 0, 0L);
        k_bnapply_t<<<dim3(Hh/32, Nn/32, Bn), dim3(32, 8)>>>(gam, bet, l, (int)(l == Ll-1));
    }

    k_decoder<<<Bn*Nn/8, 256>>>(Wdec, bdec, out);
}

// round 8
// speedup vs baseline: 6.8692x; 1.0926x over previous
#include <cuda_runtime.h>
#include <cstdint>

#define Bn   64
#define Nn   512
#define Tt   8
#define DINd 2
#define Hh   256
#define Ll   3
#define Ee   8192
#define Mm   128
#define Pout 24
#define EPSf 1e-5f

// ---------------- scratch (allocation-free) ----------------
__device__ float g_h    [Bn*Nn*Hh];
__device__ float g_hs   [Bn*Nn*Hh];
__device__ float g_hsT  [Bn*Hh*Nn];    // h_social^T, full fp32 (split on the fly)
__device__ float g_hc   [Bn*Nn*Hh];
__device__ float g_Yp   [2*Bn*Mm*Hh];  // S1 split-K partials
__device__ float g_Y    [Bn*Mm*Hh];    // combined Y, fp32
__device__ float g_ZT   [Bn*Hh*Mm];    // (Y @ theta)^T, fp32
__device__ float g_Hc   [Bn*Nn*Mm];    // raw integer counts (tf32-exact)
__device__ float g_HcT  [Bn*Mm*Nn];    // raw integer counts (tf32-exact)
__device__ float g_thT  [Ll*Hh*Hh];    // theta^T, fp32
__device__ float g_invb [Bn*Mm];
__device__ float g_invd [Bn*Nn];
__device__ int   g_cntm [Bn*Mm];
__device__ int   g_cntn [Bn*Nn];
__device__ float g_sum  [Bn*Hh];
__device__ float g_sq   [Bn*Hh];

// ================= helpers =================
__device__ __forceinline__ uint32_t smem_u32(const void* p) {
    uint32_t a;
    asm("{ .reg .u64 t; cvta.to.shared.u64 t, %1; cvt.u32.u64 %0, t; }" : "=r"(a) : "l"(p));
    return a;
}
__device__ __forceinline__ uint32_t tf32bits(float x) {
    uint32_t u;
    asm("cvt.rna.tf32.f32 %0, %1;" : "=r"(u) : "f"(x));
    return u;
}
__device__ __forceinline__ void split_tf32(float v, uint32_t& hi, uint32_t& lo) {
    hi = tf32bits(v);
    lo = tf32bits(v - __uint_as_float(hi));
}
#define CP16(dst, src) asm volatile("cp.async.cg.shared.global [%0], [%1], 16;" :: "r"(dst), "l"(src) : "memory")
#define CPCOMMIT()     asm volatile("cp.async.commit_group;" ::: "memory")
#define CPWAIT1()      asm volatile("cp.async.wait_group 1;" ::: "memory")

__device__ __forceinline__ void mma_tf32(float* c, const uint32_t* a, const uint32_t* b) {
    asm volatile(
        "mma.sync.aligned.m16n8k8.row.col.f32.tf32.tf32.f32 "
        "{%0,%1,%2,%3}, {%4,%5,%6,%7}, {%8,%9}, {%0,%1,%2,%3};"
        : "+f"(c[0]), "+f"(c[1]), "+f"(c[2]), "+f"(c[3])
        : "r"(a[0]), "r"(a[1]), "r"(a[2]), "r"(a[3]), "r"(b[0]), "r"(b[1]));
}

// ================= error-compensated tf32 mma.sync GEMM, on-the-fly split =================
// Block tile 128x64 (M x N), BK=32, 4 warps (2x2), warp tile 64x32.
// Operands stored fp32 K-major; hi/lo tf32 split computed in fragment loads.
// SPLITA=0: C = A@Bhi^T + A@Blo^T        (A exact in tf32: integer counts)
// SPLITA=1: C = Ah@Bh^T + Ah@Bl^T + Al@Bh^T
// smem: A 2-stage 32KB + B 2-stage 16KB = 48KB.
// koffY != 0: split-K mode (blockIdx.y picks K-slice and partial output buffer).
// Epilogue: optional rowscale, bias, fused BN stats via shfl + global atomics.
#define AFL 4096   // A tile floats (128*32)
#define BFL 2048   // B tile floats (64*32)
#define O_B 8192

template<int SPLITA>
__global__ void __launch_bounds__(128)
k_mma2(const float* __restrict__ Ag, const float* __restrict__ Bg,
       float* __restrict__ Cg,
       const float* __restrict__ rowscale, const float* __restrict__ bias,
       int K, int lda, int ldb, int N, int M,
       long sA, long sB, long sC, int dostats,
       int koffY, long cOffY) {
    extern __shared__ float sm[];
    uint32_t sbase = smem_u32(sm);

    int tid = threadIdx.x, lane = tid & 31, wid = tid >> 5;
    int wm = wid >> 1, wn = wid & 1;
    int col0 = blockIdx.x * 64;
    int row0, k_base;
    long cadd;
    if (koffY) { row0 = 0; k_base = blockIdx.y * koffY; cadd = (long)blockIdx.y * cOffY; }
    else       { row0 = blockIdx.y * 128; k_base = 0; cadd = 0; }
    int z = blockIdx.z;
    const float* A = Ag + (size_t)z * sA + k_base;
    const float* B = Bg + (size_t)z * sB + k_base;
    float* C = Cg + (size_t)z * sC + cadd;

    int cr = tid >> 3;                 // 0..15
    int cc = (tid & 7) * 4;

    float acc[4][4][4];
#pragma unroll
    for (int i = 0; i < 4; i++)
#pragma unroll
        for (int j = 0; j < 4; j++)
#pragma unroll
            for (int q = 0; q < 4; q++) acc[i][j][q] = 0.f;

    int nkb = K >> 5;

#pragma unroll
    for (int s = 0; s < 2; s++) {
        int kk = s * 32;
#pragma unroll
        for (int i = 0; i < 8; i++) {             // A: 128 rows
            int rr = cr + i * 16;
            uint32_t so = (uint32_t)(s * AFL + rr * 32 + (cc ^ ((rr & 7) * 4))) * 4;
            CP16(sbase + so, A + (size_t)(row0 + rr) * lda + kk + cc);
        }
#pragma unroll
        for (int i = 0; i < 4; i++) {             // B: 64 rows
            int rr = cr + i * 16;
            uint32_t so = (uint32_t)(O_B + s * BFL + rr * 32 + (cc ^ ((rr & 7) * 4))) * 4;
            CP16(sbase + so, B + (size_t)(col0 + rr) * ldb + kk + cc);
        }
        CPCOMMIT();
    }

    int g = lane >> 2, t = lane & 3;
    int arow = (wm * 64 + g) * 32;
    int brow = (wn * 32 + g) * 32;
    int sxor = g * 4;

    for (int kb = 0; kb < nkb; kb++) {
        int s = kb & 1;
        CPWAIT1();
        __syncthreads();

        const float* At = sm + s * AFL;
        const float* Bt = sm + O_B + s * BFL;

#pragma unroll
        for (int ks = 0; ks < 4; ks++) {
            int kc  = ks * 8 + t;
            int xc0 = kc ^ sxor;
            int xc4 = (kc + 4) ^ sxor;
            uint32_t a[4][4], al[4][4], bh[4][2], bl[4][2];
#pragma unroll
            for (int mf = 0; mf < 4; mf++) {
                int o = arow + mf * 512;
                float v0 = At[o + xc0];
                float v1 = At[o + 256 + xc0];
                float v2 = At[o + xc4];
                float v3 = At[o + 256 + xc4];
                if (SPLITA) {
                    split_tf32(v0, a[mf][0], al[mf][0]);
                    split_tf32(v1, a[mf][1], al[mf][1]);
                    split_tf32(v2, a[mf][2], al[mf][2]);
                    split_tf32(v3, a[mf][3], al[mf][3]);
                } else {
                    a[mf][0] = __float_as_uint(v0);
                    a[mf][1] = __float_as_uint(v1);
                    a[mf][2] = __float_as_uint(v2);
                    a[mf][3] = __float_as_uint(v3);
                }
            }
#pragma unroll
            for (int nf = 0; nf < 4; nf++) {
                int o = brow + nf * 256;
                split_tf32(Bt[o + xc0], bh[nf][0], bl[nf][0]);
                split_tf32(Bt[o + xc4], bh[nf][1], bl[nf][1]);
            }
#pragma unroll
            for (int mf = 0; mf < 4; mf++)
#pragma unroll
                for (int nf = 0; nf < 4; nf++)
                    mma_tf32(acc[mf][nf], a[mf], bh[nf]);
#pragma unroll
            for (int mf = 0; mf < 4; mf++)
#pragma unroll
                for (int nf = 0; nf < 4; nf++)
                    mma_tf32(acc[mf][nf], a[mf], bl[nf]);
            if (SPLITA) {
#pragma unroll
                for (int mf = 0; mf < 4; mf++)
#pragma unroll
                    for (int nf = 0; nf < 4; nf++)
                        mma_tf32(acc[mf][nf], al[mf], bh[nf]);
            }
        }
        __syncthreads();

        if (kb + 2 < nkb) {
            int kk = (kb + 2) * 32;
#pragma unroll
            for (int i = 0; i < 8; i++) {
                int rr = cr + i * 16;
                uint32_t so = (uint32_t)(s * AFL + rr * 32 + (cc ^ ((rr & 7) * 4))) * 4;
                CP16(sbase + so, A + (size_t)(row0 + rr) * lda + kk + cc);
            }
#pragma unroll
            for (int i = 0; i < 4; i++) {
                int rr = cr + i * 16;
                uint32_t so = (uint32_t)(O_B + s * BFL + rr * 32 + (cc ^ ((rr & 7) * 4))) * 4;
                CP16(sbase + so, B + (size_t)(col0 + rr) * ldb + kk + cc);
            }
        }
        CPCOMMIT();
    }

    // ---------------- epilogue ----------------
    const float* rsb = rowscale ? rowscale + (size_t)z * M : nullptr;
    float cs[8], cq[8];
    if (dostats) {
#pragma unroll
        for (int i = 0; i < 8; i++) { cs[i] = 0.f; cq[i] = 0.f; }
    }
#pragma unroll
    for (int mf = 0; mf < 4; mf++) {
        int rr = row0 + wm * 64 + mf * 16 + g;
        float rs0 = rsb ? rsb[rr]     : 1.f;
        float rs1 = rsb ? rsb[rr + 8] : 1.f;
#pragma unroll
        for (int nf = 0; nf < 4; nf++) {
            int ccg = col0 + wn * 32 + nf * 8 + t * 2;
            float c0 = acc[mf][nf][0] * rs0, c1 = acc[mf][nf][1] * rs0;
            float c2 = acc[mf][nf][2] * rs1, c3 = acc[mf][nf][3] * rs1;
            if (bias) {
                float b0 = bias[ccg], b1 = bias[ccg + 1];
                c0 += b0; c1 += b1; c2 += b0; c3 += b1;
            }
            if (dostats) {
                cs[nf*2]   += c0 + c2;  cs[nf*2+1] += c1 + c3;
                cq[nf*2]   += c0*c0 + c2*c2;
                cq[nf*2+1] += c1*c1 + c3*c3;
            }
            *reinterpret_cast<float2*>(&C[(size_t)rr * N + ccg])       = make_float2(c0, c1);
            *reinterpret_cast<float2*>(&C[(size_t)(rr + 8) * N + ccg]) = make_float2(c2, c3);
        }
    }
    if (dostats) {
#pragma unroll
        for (int off = 4; off <= 16; off <<= 1) {
#pragma unroll
            for (int i = 0; i < 8; i++) {
                cs[i] += __shfl_xor_sync(0xffffffffu, cs[i], off);
                cq[i] += __shfl_xor_sync(0xffffffffu, cq[i], off);
            }
        }
        if (g == 0) {
#pragma unroll
            for (int nf = 0; nf < 4; nf++) {
#pragma unroll
                for (int j = 0; j < 2; j++) {
                    int ccg = col0 + wn * 32 + nf * 8 + t * 2 + j;
                    atomicAdd(&g_sum[z * Hh + ccg], cs[nf*2+j]);
                    atomicAdd(&g_sq [z * Hh + ccg], cq[nf*2+j]);
                }
            }
        }
    }
}

// ---------------- S1 split-K combine: Y = invb * (P0 + P1) ----------------
__global__ void k_combineY() {
    int i = blockIdx.x * 256 + threadIdx.x;
    int b   = i >> 15;
    int row = (i >> 8) & (Mm - 1);
    g_Y[i] = (g_Yp[i] + g_Yp[i + Bn*Mm*Hh]) * g_invb[b * Mm + row];
}

// ---------------- encoder ----------------
__global__ void k_encoder(const float* __restrict__ obs,
                          const float* __restrict__ Wenc,
                          const float* __restrict__ benc) {
    int bn = blockIdx.x;
    int h  = threadIdx.x;
    int b  = bn >> 9, n = bn & (Nn - 1);
    __shared__ float srow[Tt*DINd];
    if (h < Tt*DINd) srow[h] = obs[bn*Tt*DINd + h];
    __syncthreads();
    float w0 = Wenc[h], w1 = Wenc[Hh + h], bb = benc[h];
    float acc = 0.f;
#pragma unroll
    for (int t = 0; t < Tt; t++) {
        float v = fmaf(srow[2*t], w0, fmaf(srow[2*t+1], w1, bb));
        acc += fmaxf(v, 0.f);
    }
    float r = acc * (1.f / Tt);
    g_h[(size_t)bn*Hh + h] = r;
    g_hsT[((size_t)b*Hh + h)*Nn + n] = r;
}

// ---------------- incidence build (raw counts) ----------------
__global__ void k_zero_dense() {
    int i = blockIdx.x * blockDim.x + threadIdx.x;
    g_Hc[i]  = 0.f;
    g_HcT[i] = 0.f;
    if (i < Bn*Mm) g_cntm[i] = 0;
    if (i < Bn*Nn) g_cntn[i] = 0;
}
__global__ void k_build(const int* __restrict__ idx) {
    int i = blockIdx.x * blockDim.x + threadIdx.x;
    int b = i >> 13, e = i & (Ee - 1);
    int n = idx[b*2*Ee + e];
    int m = idx[b*2*Ee + Ee + e];
    atomicAdd(&g_Hc [((size_t)b*Nn + n)*Mm + m], 1.f);
    atomicAdd(&g_HcT[((size_t)b*Mm + m)*Nn + n], 1.f);
    atomicAdd(&g_cntn[b*Nn + n], 1);
    atomicAdd(&g_cntm[b*Mm + m], 1);
}
__global__ void k_invdeg() {
    int i = blockIdx.x * blockDim.x + threadIdx.x;
    if (i < Bn*Mm) g_invb[i] = 1.f / fmaxf((float)g_cntm[i], 1.f);
    if (i < Bn*Nn) g_invd[i] = 1.f / fmaxf((float)g_cntn[i], 1.f);
}

// ---------------- theta transpose ----------------
__global__ void k_trans_theta(const float* __restrict__ thetas) {
    __shared__ float t[32][33];
    int l  = blockIdx.z;
    int x0 = blockIdx.x * 32, y0 = blockIdx.y * 32;
    int tx = threadIdx.x, ty = threadIdx.y;
    const float* src = thetas + (size_t)l * Hh * Hh;
#pragma unroll
    for (int j = 0; j < 4; j++)
        t[ty + j*8][tx] = src[(size_t)(y0 + ty + j*8)*Hh + x0 + tx];
    __syncthreads();
#pragma unroll
    for (int j = 0; j < 4; j++)
        g_thT[(size_t)l*Hh*Hh + (size_t)(x0 + ty + j*8)*Hh + y0 + tx] = t[tx][ty + j*8];
}

__global__ void k_zero_stats() {
    int i = blockIdx.x * blockDim.x + threadIdx.x;
    g_sum[i] = 0.f;
    g_sq[i]  = 0.f;
}

// ---------------- BN apply + relu -> hsT (+ hs row-major last layer) ----------------
__global__ void k_bnapply_t(const float* __restrict__ gam,
                            const float* __restrict__ bet, int l, int writeRow) {
    __shared__ float t[32][33];
    int b  = blockIdx.z;
    int h0 = blockIdx.x * 32, n0 = blockIdx.y * 32;
    int tx = threadIdx.x, ty = threadIdx.y;
    int h  = h0 + tx;
    float mean = g_sum[b*Hh + h] * (1.f / Nn);
    float var  = g_sq [b*Hh + h] * (1.f / Nn) - mean*mean;
    float rstd = rsqrtf(var + EPSf);
    float gm = gam[l*Hh + h], bt = bet[l*Hh + h];
#pragma unroll
    for (int j = 0; j < 4; j++) {
        int n = n0 + ty + j*8;
        size_t ix = ((size_t)b*Nn + n)*Hh + h;
        float v = fmaxf((g_hc[ix] - mean) * rstd * gm + bt, 0.f);
        if (writeRow) g_hs[ix] = v;
        t[ty + j*8][tx] = v;
    }
    __syncthreads();
#pragma unroll
    for (int j = 0; j < 4; j++)
        g_hsT[((size_t)b*Hh + h0 + ty + j*8)*Nn + n0 + tx] = t[tx][ty + j*8];
}

// ---------------- decoder ----------------
__global__ void k_decoder(const float* __restrict__ Wdec,
                          const float* __restrict__ bdec,
                          float* __restrict__ out) {
    __shared__ float Ws[Hh*Pout + 32];
    int tid = threadIdx.x;
    for (int i = tid; i < Hh*Pout; i += 256) Ws[i] = Wdec[i];
    __syncthreads();
    int row  = blockIdx.x * 8 + (tid >> 5);
    int lane = tid & 31;
    const float* xh = g_h  + (size_t)row * Hh;
    const float* xs = g_hs + (size_t)row * Hh;
    float xr[8];
#pragma unroll
    for (int j = 0; j < 8; j++) xr[j] = xh[lane + j*32] + xs[lane + j*32];
    float acc = 0.f;
    int wl = (lane < Pout) ? lane : 0;
#pragma unroll 4
    for (int k = 0; k < Hh; k++) {
        float xv = __shfl_sync(0xffffffffu, xr[k >> 5], k & 31);
        acc = fmaf(xv, Ws[k*Pout + wl], acc);
    }
    if (lane < Pout)
        out[(size_t)row*Pout + lane] = acc + bdec[lane];
}

// ---------------- launch ----------------
extern "C" void kernel_launch(void* const* d_in, const int* in_sizes, int n_in,
                              void* d_out, int out_size) {
    const float* obs    = (const float*)d_in[0];
    const int*   idx    = (const int*)  d_in[1];
    const float* Wenc   = (const float*)d_in[2];
    const float* benc   = (const float*)d_in[3];
    const float* thetas = (const float*)d_in[4];
    const float* cbias  = (const float*)d_in[5];
    const float* gam    = (const float*)d_in[6];
    const float* bet    = (const float*)d_in[7];
    const float* Wdec   = (const float*)d_in[8];
    const float* bdec   = (const float*)d_in[9];
    float* out = (float*)d_out;

    float *dHc, *dHcT, *dhsT, *dYp, *dY, *dZT, *dhc, *dthT, *dinvb, *dinvd;
    cudaGetSymbolAddress((void**)&dHc,   g_Hc);
    cudaGetSymbolAddress((void**)&dHcT,  g_HcT);
    cudaGetSymbolAddress((void**)&dhsT,  g_hsT);
    cudaGetSymbolAddress((void**)&dYp,   g_Yp);
    cudaGetSymbolAddress((void**)&dY,    g_Y);
    cudaGetSymbolAddress((void**)&dZT,   g_ZT);
    cudaGetSymbolAddress((void**)&dhc,   g_hc);
    cudaGetSymbolAddress((void**)&dthT,  g_thT);
    cudaGetSymbolAddress((void**)&dinvb, g_invb);
    cudaGetSymbolAddress((void**)&dinvd, g_invd);

    const int SMEM_G = (2*AFL + 2*BFL) * 4;   // 48KB
    cudaFuncSetAttribute(k_mma2<0>, cudaFuncAttributeMaxDynamicSharedMemorySize, SMEM_G);
    cudaFuncSetAttribute(k_mma2<1>, cudaFuncAttributeMaxDynamicSharedMemorySize, SMEM_G);

    k_encoder<<<Bn*Nn, Hh>>>(obs, Wenc, benc);                     // 1
    k_zero_dense<<<Bn*Nn*Mm/256, 256>>>();                         // 2
    k_build<<<Bn*Ee/256, 256>>>(idx);                              // 3

    for (int l = 0; l < Ll; l++) {
        // S1 split-K: Yp[y] = HcT[:, y*256:+256] @ hsT[:, y*256:+256]^T
        k_mma2<0><<<dim3(4, 2, Bn), 128, SMEM_G>>>(dHcT, dhsT, dYp,
            nullptr, nullptr, 256, Nn, Nn, Hh, Mm,
            (long)Mm*Nn, (long)Hh*Nn, (long)Mm*Hh, 0, 256, (long)Bn*Mm*Hh);   // 4 on l==0
        if (l == 0) {
            k_invdeg<<<(Bn*Nn + 255)/256, 256>>>();
            k_trans_theta<<<dim3(Hh/32, Hh/32, Ll), dim3(32, 8)>>>(thetas);
        }
        k_zero_stats<<<Bn*Hh/256, 256>>>();
        k_combineY<<<Bn*Mm*Hh/256, 256>>>();
        // S2: ZT[b](256x128) = thT_l(256x256) @ Y[b](128x256)^T
        k_mma2<1><<<dim3(2, 2, Bn), 128, SMEM_G>>>(dthT + (size_t)l*Hh*Hh, dY, dZT,
            nullptr, nullptr, 256, Hh, Hh, Mm, Hh,
            0L, (long)Mm*Hh, (long)Hh*Mm, 0, 0, 0L);
        // S3: hc[b](512x256) = Dinv*(Hc[b](512x128) @ ZT[b](256x128)^T) + bias, fused BN stats
        k_mma2<0><<<dim3(4, 4, Bn), 128, SMEM_G>>>(dHc, dZT, dhc,
            dinvd, cbias + (size_t)l*Hh, 128, Mm, Mm, Hh, Nn,
            (long)Nn*Mm, (long)Hh*Mm, (long)Nn*Hh, 1, 0, 0L);
        k_bnapply_t<<<dim3(Hh/32, Nn/32, Bn), dim3(32, 8)>>>(gam, bet, l, (int)(l == Ll-1));
    }

    k_decoder<<<Bn*Nn/8, 256>>>(Wdec, bdec, out);
}

// round 9
// speedup vs baseline: 7.0798x; 1.0306x over previous
#include <cuda_runtime.h>
#include <cstdint>

#define Bn   64
#define Nn   512
#define Tt   8
#define DINd 2
#define Hh   256
#define Ll   3
#define Ee   8192
#define Mm   128
#define Pout 24
#define EPSf 1e-5f

// ---------------- scratch (allocation-free) ----------------
__device__ float g_h    [Bn*Nn*Hh];
__device__ float g_hs   [Bn*Nn*Hh];
__device__ float g_hsT  [Bn*Hh*Nn];    // h_social^T, fp32
__device__ float g_hc   [Bn*Nn*Hh];
__device__ float g_Yp   [2*Bn*Mm*Hh];  // S1 split-K partials (consumed by S2)
__device__ float g_ZT   [Bn*Hh*Mm];    // (Y @ theta)^T, fp32
__device__ float g_Hc   [Bn*Nn*Mm];    // raw integer counts (tf32-exact)
__device__ float g_HcT  [Bn*Mm*Nn];    // raw integer counts (tf32-exact)
__device__ float g_thT  [Ll*Hh*Hh];    // theta^T, fp32
__device__ float g_invb [Bn*Mm];
__device__ float g_invd [Bn*Nn];
__device__ int   g_cntm [Bn*Mm];
__device__ int   g_cntn [Bn*Nn];
__device__ float g_sum  [Bn*Hh];
__device__ float g_sq   [Bn*Hh];

// ================= helpers =================
__device__ __forceinline__ uint32_t smem_u32(const void* p) {
    uint32_t a;
    asm("{ .reg .u64 t; cvta.to.shared.u64 t, %1; cvt.u32.u64 %0, t; }" : "=r"(a) : "l"(p));
    return a;
}
__device__ __forceinline__ uint32_t tf32bits(float x) {
    uint32_t u;
    asm("cvt.rna.tf32.f32 %0, %1;" : "=r"(u) : "f"(x));
    return u;
}
__device__ __forceinline__ void split_tf32(float v, uint32_t& hi, uint32_t& lo) {
    hi = tf32bits(v);
    lo = tf32bits(v - __uint_as_float(hi));
}
#define CP16(dst, src) asm volatile("cp.async.cg.shared.global [%0], [%1], 16;" :: "r"(dst), "l"(src) : "memory")
#define CPCOMMIT()     asm volatile("cp.async.commit_group;" ::: "memory")
#define CPWAIT1()      asm volatile("cp.async.wait_group 1;" ::: "memory")

__device__ __forceinline__ void mma_tf32(float* c, const uint32_t* a, const uint32_t* b) {
    asm volatile(
        "mma.sync.aligned.m16n8k8.row.col.f32.tf32.tf32.f32 "
        "{%0,%1,%2,%3}, {%4,%5,%6,%7}, {%8,%9}, {%0,%1,%2,%3};"
        : "+f"(c[0]), "+f"(c[1]), "+f"(c[2]), "+f"(c[3])
        : "r"(a[0]), "r"(a[1]), "r"(a[2]), "r"(a[3]), "r"(b[0]), "r"(b[1]));
}

// ================= error-compensated tf32 mma.sync GEMM, on-the-fly split =================
// Block tile 128x64 (M x N), BK=32, 4 warps (2x2), warp tile 64x32.
// Operands fp32 K-major; hi/lo tf32 split computed in fragment loads.
// SPLITA=0: C = A@Bhi^T + A@Blo^T        (A exact in tf32)
// SPLITA=1: C = Ah@Bh^T + Ah@Bl^T + Al@Bh^T
// COMBINE=1: B element = (B[x] + B[bOff2 + x]) * rowscaleB[row]  (split-K merge of S1)
// koffY != 0: split-K mode (blockIdx.y picks K-slice + partial output buffer).
// Epilogue: optional rowscale, bias, fused BN stats via shfl + global atomics.
#define AFL 4096   // A tile floats (128*32)
#define BFL 2048   // B tile floats (64*32)
#define O_B  8192
#define O_B2 12288

template<int SPLITA, int COMBINE>
__global__ void __launch_bounds__(128, 4)
k_mma2(const float* __restrict__ Ag, const float* __restrict__ Bg,
       float* __restrict__ Cg,
       const float* __restrict__ rowscale, const float* __restrict__ bias,
       const float* __restrict__ rowscaleB, long bOff2,
       int K, int lda, int ldb, int N, int M,
       long sA, long sB, long sC, int dostats,
       int koffY, long cOffY) {
    extern __shared__ float sm[];
    uint32_t sbase = smem_u32(sm);

    int tid = threadIdx.x, lane = tid & 31, wid = tid >> 5;
    int wm = wid >> 1, wn = wid & 1;
    int col0 = blockIdx.x * 64;
    int row0, k_base;
    long cadd;
    if (koffY) { row0 = 0; k_base = blockIdx.y * koffY; cadd = (long)blockIdx.y * cOffY; }
    else       { row0 = blockIdx.y * 128; k_base = 0; cadd = 0; }
    int z = blockIdx.z;
    const float* A  = Ag + (size_t)z * sA + k_base;
    const float* B  = Bg + (size_t)z * sB + k_base;
    const float* B2 = COMBINE ? (Bg + bOff2 + (size_t)z * sB + k_base) : nullptr;
    float* C = Cg + (size_t)z * sC + cadd;

    int cr = tid >> 3;                 // 0..15
    int cc = (tid & 7) * 4;

    float acc[4][4][4];
#pragma unroll
    for (int i = 0; i < 4; i++)
#pragma unroll
        for (int j = 0; j < 4; j++)
#pragma unroll
            for (int q = 0; q < 4; q++) acc[i][j][q] = 0.f;

    int nkb = K >> 5;
    int g = lane >> 2, t = lane & 3;

    float rsB[4];
    if (COMBINE) {
#pragma unroll
        for (int nf = 0; nf < 4; nf++)
            rsB[nf] = rowscaleB[(size_t)z * Mm + col0 + wn * 32 + nf * 8 + g];
    }

#pragma unroll
    for (int s = 0; s < 2; s++) {
        int kk = s * 32;
#pragma unroll
        for (int i = 0; i < 8; i++) {             // A: 128 rows
            int rr = cr + i * 16;
            uint32_t so = (uint32_t)(s * AFL + rr * 32 + (cc ^ ((rr & 7) * 4))) * 4;
            CP16(sbase + so, A + (size_t)(row0 + rr) * lda + kk + cc);
        }
#pragma unroll
        for (int i = 0; i < 4; i++) {             // B: 64 rows
            int rr = cr + i * 16;
            uint32_t sw = (uint32_t)(rr * 32 + (cc ^ ((rr & 7) * 4)));
            size_t gb = (size_t)(col0 + rr) * ldb + kk + cc;
            CP16(sbase + (uint32_t)(O_B + s * BFL + sw) * 4, B + gb);
            if (COMBINE) CP16(sbase + (uint32_t)(O_B2 + s * BFL + sw) * 4, B2 + gb);
        }
        CPCOMMIT();
    }

    int arow = (wm * 64 + g) * 32;
    int brow = (wn * 32 + g) * 32;
    int sxor = g * 4;

    for (int kb = 0; kb < nkb; kb++) {
        int s = kb & 1;
        CPWAIT1();
        __syncthreads();

        const float* At  = sm + s * AFL;
        const float* Bt  = sm + O_B  + s * BFL;
        const float* Bt2 = sm + O_B2 + s * BFL;

#pragma unroll
        for (int ks = 0; ks < 4; ks++) {
            int kc  = ks * 8 + t;
            int xc0 = kc ^ sxor;
            int xc4 = (kc + 4) ^ sxor;
            uint32_t a[4][4], al[4][4], bh[4][2], bl[4][2];
#pragma unroll
            for (int mf = 0; mf < 4; mf++) {
                int o = arow + mf * 512;
                float v0 = At[o + xc0];
                float v1 = At[o + 256 + xc0];
                float v2 = At[o + xc4];
                float v3 = At[o + 256 + xc4];
                if (SPLITA) {
                    split_tf32(v0, a[mf][0], al[mf][0]);
                    split_tf32(v1, a[mf][1], al[mf][1]);
                    split_tf32(v2, a[mf][2], al[mf][2]);
                    split_tf32(v3, a[mf][3], al[mf][3]);
                } else {
                    a[mf][0] = __float_as_uint(v0);
                    a[mf][1] = __float_as_uint(v1);
                    a[mf][2] = __float_as_uint(v2);
                    a[mf][3] = __float_as_uint(v3);
                }
            }
#pragma unroll
            for (int nf = 0; nf < 4; nf++) {
                int o = brow + nf * 256;
                float u0 = Bt[o + xc0];
                float u1 = Bt[o + xc4];
                if (COMBINE) {
                    u0 = (u0 + Bt2[o + xc0]) * rsB[nf];
                    u1 = (u1 + Bt2[o + xc4]) * rsB[nf];
                }
                split_tf32(u0, bh[nf][0], bl[nf][0]);
                split_tf32(u1, bh[nf][1], bl[nf][1]);
            }
#pragma unroll
            for (int mf = 0; mf < 4; mf++)
#pragma unroll
                for (int nf = 0; nf < 4; nf++)
                    mma_tf32(acc[mf][nf], a[mf], bh[nf]);
#pragma unroll
            for (int mf = 0; mf < 4; mf++)
#pragma unroll
                for (int nf = 0; nf < 4; nf++)
                    mma_tf32(acc[mf][nf], a[mf], bl[nf]);
            if (SPLITA) {
#pragma unroll
                for (int mf = 0; mf < 4; mf++)
#pragma unroll
                    for (int nf = 0; nf < 4; nf++)
                        mma_tf32(acc[mf][nf], al[mf], bh[nf]);
            }
        }
        __syncthreads();

        if (kb + 2 < nkb) {
            int kk = (kb + 2) * 32;
#pragma unroll
            for (int i = 0; i < 8; i++) {
                int rr = cr + i * 16;
                uint32_t so = (uint32_t)(s * AFL + rr * 32 + (cc ^ ((rr & 7) * 4))) * 4;
                CP16(sbase + so, A + (size_t)(row0 + rr) * lda + kk + cc);
            }
#pragma unroll
            for (int i = 0; i < 4; i++) {
                int rr = cr + i * 16;
                uint32_t sw = (uint32_t)(rr * 32 + (cc ^ ((rr & 7) * 4)));
                size_t gb = (size_t)(col0 + rr) * ldb + kk + cc;
                CP16(sbase + (uint32_t)(O_B + s * BFL + sw) * 4, B + gb);
                if (COMBINE) CP16(sbase + (uint32_t)(O_B2 + s * BFL + sw) * 4, B2 + gb);
            }
        }
        CPCOMMIT();
    }

    // ---------------- epilogue ----------------
    const float* rsb = rowscale ? rowscale + (size_t)z * M : nullptr;
    float cs[8], cq[8];
    if (dostats) {
#pragma unroll
        for (int i = 0; i < 8; i++) { cs[i] = 0.f; cq[i] = 0.f; }
    }
#pragma unroll
    for (int mf = 0; mf < 4; mf++) {
        int rr = row0 + wm * 64 + mf * 16 + g;
        float rs0 = rsb ? rsb[rr]     : 1.f;
        float rs1 = rsb ? rsb[rr + 8] : 1.f;
#pragma unroll
        for (int nf = 0; nf < 4; nf++) {
            int ccg = col0 + wn * 32 + nf * 8 + t * 2;
            float c0 = acc[mf][nf][0] * rs0, c1 = acc[mf][nf][1] * rs0;
            float c2 = acc[mf][nf][2] * rs1, c3 = acc[mf][nf][3] * rs1;
            if (bias) {
                float b0 = bias[ccg], b1 = bias[ccg + 1];
                c0 += b0; c1 += b1; c2 += b0; c3 += b1;
            }
            if (dostats) {
                cs[nf*2]   += c0 + c2;  cs[nf*2+1] += c1 + c3;
                cq[nf*2]   += c0*c0 + c2*c2;
                cq[nf*2+1] += c1*c1 + c3*c3;
            }
            *reinterpret_cast<float2*>(&C[(size_t)rr * N + ccg])       = make_float2(c0, c1);
            *reinterpret_cast<float2*>(&C[(size_t)(rr + 8) * N + ccg]) = make_float2(c2, c3);
        }
    }
    if (dostats) {
#pragma unroll
        for (int off = 4; off <= 16; off <<= 1) {
#pragma unroll
            for (int i = 0; i < 8; i++) {
                cs[i] += __shfl_xor_sync(0xffffffffu, cs[i], off);
                cq[i] += __shfl_xor_sync(0xffffffffu, cq[i], off);
            }
        }
        if (g == 0) {
#pragma unroll
            for (int nf = 0; nf < 4; nf++) {
#pragma unroll
                for (int j = 0; j < 2; j++) {
                    int ccg = col0 + wn * 32 + nf * 8 + t * 2 + j;
                    atomicAdd(&g_sum[z * Hh + ccg], cs[nf*2+j]);
                    atomicAdd(&g_sq [z * Hh + ccg], cq[nf*2+j]);
                }
            }
        }
    }
}

// ---------------- encoder ----------------
__global__ void k_encoder(const float* __restrict__ obs,
                          const float* __restrict__ Wenc,
                          const float* __restrict__ benc) {
    int bn = blockIdx.x;
    int h  = threadIdx.x;
    int b  = bn >> 9, n = bn & (Nn - 1);
    __shared__ float srow[Tt*DINd];
    if (h < Tt*DINd) srow[h] = obs[bn*Tt*DINd + h];
    __syncthreads();
    float w0 = Wenc[h], w1 = Wenc[Hh + h], bb = benc[h];
    float acc = 0.f;
#pragma unroll
    for (int t = 0; t < Tt; t++) {
        float v = fmaf(srow[2*t], w0, fmaf(srow[2*t+1], w1, bb));
        acc += fmaxf(v, 0.f);
    }
    float r = acc * (1.f / Tt);
    g_h[(size_t)bn*Hh + h] = r;
    g_hsT[((size_t)b*Hh + h)*Nn + n] = r;
}

// ---------------- incidence build (raw counts) ----------------
__global__ void k_zero_dense() {
    int i = blockIdx.x * blockDim.x + threadIdx.x;
    g_Hc[i]  = 0.f;
    g_HcT[i] = 0.f;
    if (i < Bn*Mm) g_cntm[i] = 0;
    if (i < Bn*Nn) g_cntn[i] = 0;
}
__global__ void k_build(const int* __restrict__ idx) {
    int i = blockIdx.x * blockDim.x + threadIdx.x;
    int b = i >> 13, e = i & (Ee - 1);
    int n = idx[b*2*Ee + e];
    int m = idx[b*2*Ee + Ee + e];
    atomicAdd(&g_Hc [((size_t)b*Nn + n)*Mm + m], 1.f);
    atomicAdd(&g_HcT[((size_t)b*Mm + m)*Nn + n], 1.f);
    atomicAdd(&g_cntn[b*Nn + n], 1);
    atomicAdd(&g_cntm[b*Mm + m], 1);
}
__global__ void k_invdeg() {
    int i = blockIdx.x * blockDim.x + threadIdx.x;
    if (i < Bn*Mm) g_invb[i] = 1.f / fmaxf((float)g_cntm[i], 1.f);
    if (i < Bn*Nn) g_invd[i] = 1.f / fmaxf((float)g_cntn[i], 1.f);
}

// ---------------- theta transpose ----------------
__global__ void k_trans_theta(const float* __restrict__ thetas) {
    __shared__ float t[32][33];
    int l  = blockIdx.z;
    int x0 = blockIdx.x * 32, y0 = blockIdx.y * 32;
    int tx = threadIdx.x, ty = threadIdx.y;
    const float* src = thetas + (size_t)l * Hh * Hh;
#pragma unroll
    for (int j = 0; j < 4; j++)
        t[ty + j*8][tx] = src[(size_t)(y0 + ty + j*8)*Hh + x0 + tx];
    __syncthreads();
#pragma unroll
    for (int j = 0; j < 4; j++)
        g_thT[(size_t)l*Hh*Hh + (size_t)(x0 + ty + j*8)*Hh + y0 + tx] = t[tx][ty + j*8];
}

__global__ void k_zero_stats() {
    int i = blockIdx.x * blockDim.x + threadIdx.x;
    g_sum[i] = 0.f;
    g_sq[i]  = 0.f;
}

// ---------------- BN apply + relu -> hsT (or hs row-major on last layer) ----------------
__global__ void k_bnapply_t(const float* __restrict__ gam,
                            const float* __restrict__ bet, int l, int lastLayer) {
    __shared__ float t[32][33];
    int b  = blockIdx.z;
    int h0 = blockIdx.x * 32, n0 = blockIdx.y * 32;
    int tx = threadIdx.x, ty = threadIdx.y;
    int h  = h0 + tx;
    float mean = g_sum[b*Hh + h] * (1.f / Nn);
    float var  = g_sq [b*Hh + h] * (1.f / Nn) - mean*mean;
    float rstd = rsqrtf(var + EPSf);
    float gm = gam[l*Hh + h], bt = bet[l*Hh + h];
#pragma unroll
    for (int j = 0; j < 4; j++) {
        int n = n0 + ty + j*8;
        size_t ix = ((size_t)b*Nn + n)*Hh + h;
        float v = fmaxf((g_hc[ix] - mean) * rstd * gm + bt, 0.f);
        if (lastLayer) g_hs[ix] = v;
        else           t[ty + j*8][tx] = v;
    }
    if (!lastLayer) {
        __syncthreads();
#pragma unroll
        for (int j = 0; j < 4; j++)
            g_hsT[((size_t)b*Hh + h0 + ty + j*8)*Nn + n0 + tx] = t[tx][ty + j*8];
    }
}

// ---------------- decoder ----------------
__global__ void k_decoder(const float* __restrict__ Wdec,
                          const float* __restrict__ bdec,
                          float* __restrict__ out) {
    __shared__ float Ws[Hh*Pout + 32];
    int tid = threadIdx.x;
    for (int i = tid; i < Hh*Pout; i += 256) Ws[i] = Wdec[i];
    __syncthreads();
    int row  = blockIdx.x * 8 + (tid >> 5);
    int lane = tid & 31;
    const float* xh = g_h  + (size_t)row * Hh;
    const float* xs = g_hs + (size_t)row * Hh;
    float xr[8];
#pragma unroll
    for (int j = 0; j < 8; j++) xr[j] = xh[lane + j*32] + xs[lane + j*32];
    float acc = 0.f;
    int wl = (lane < Pout) ? lane : 0;
#pragma unroll 4
    for (int k = 0; k < Hh; k++) {
        float xv = __shfl_sync(0xffffffffu, xr[k >> 5], k & 31);
        acc = fmaf(xv, Ws[k*Pout + wl], acc);
    }
    if (lane < Pout)
        out[(size_t)row*Pout + lane] = acc + bdec[lane];
}

// ---------------- launch ----------------
extern "C" void kernel_launch(void* const* d_in, const int* in_sizes, int n_in,
                              void* d_out, int out_size) {
    const float* obs    = (const float*)d_in[0];
    const int*   idx    = (const int*)  d_in[1];
    const float* Wenc   = (const float*)d_in[2];
    const float* benc   = (const float*)d_in[3];
    const float* thetas = (const float*)d_in[4];
    const float* cbias  = (const float*)d_in[5];
    const float* gam    = (const float*)d_in[6];
    const float* bet    = (const float*)d_in[7];
    const float* Wdec   = (const float*)d_in[8];
    const float* bdec   = (const float*)d_in[9];
    float* out = (float*)d_out;

    float *dHc, *dHcT, *dhsT, *dYp, *dZT, *dhc, *dthT, *dinvb, *dinvd;
    cudaGetSymbolAddress((void**)&dHc,   g_Hc);
    cudaGetSymbolAddress((void**)&dHcT,  g_HcT);
    cudaGetSymbolAddress((void**)&dhsT,  g_hsT);
    cudaGetSymbolAddress((void**)&dYp,   g_Yp);
    cudaGetSymbolAddress((void**)&dZT,   g_ZT);
    cudaGetSymbolAddress((void**)&dhc,   g_hc);
    cudaGetSymbolAddress((void**)&dthT,  g_thT);
    cudaGetSymbolAddress((void**)&dinvb, g_invb);
    cudaGetSymbolAddress((void**)&dinvd, g_invd);

    const int SMEM_G = (2*AFL + 2*BFL) * 4;   // 48KB
    const int SMEM_C = (2*AFL + 4*BFL) * 4;   // 64KB (COMBINE)
    cudaFuncSetAttribute((const void*)k_mma2<0,0>, cudaFuncAttributeMaxDynamicSharedMemorySize, SMEM_G);
    cudaFuncSetAttribute((const void*)k_mma2<1,1>, cudaFuncAttributeMaxDynamicSharedMemorySize, SMEM_C);

    k_encoder<<<Bn*Nn, Hh>>>(obs, Wenc, benc);                     // 1
    k_zero_dense<<<Bn*Nn*Mm/256, 256>>>();                         // 2
    k_build<<<Bn*Ee/256, 256>>>(idx);                              // 3

    for (int l = 0; l < Ll; l++) {
        // S1 split-K: Yp[y] = HcT[:, y*256:+256] @ hsT[:, y*256:+256]^T
        k_mma2<0,0><<<dim3(4, 2, Bn), 128, SMEM_G>>>(dHcT, dhsT, dYp,
            nullptr, nullptr, nullptr, 0L,
            256, Nn, Nn, Hh, Mm,
            (long)Mm*Nn, (long)Hh*Nn, (long)Mm*Hh, 0, 256, (long)Bn*Mm*Hh);
        if (l == 0) {
            k_invdeg<<<(Bn*Nn + 255)/256, 256>>>();
            k_trans_theta<<<dim3(Hh/32, Hh/32, Ll), dim3(32, 8)>>>(thetas);
        }
        k_zero_stats<<<Bn*Hh/256, 256>>>();
        // S2: ZT[b](256x128) = thT_l(256x256) @ [invb*(Yp0+Yp1)][b](128x256)^T
        k_mma2<1,1><<<dim3(2, 2, Bn), 128, SMEM_C>>>(dthT + (size_t)l*Hh*Hh, dYp, dZT,
            nullptr, nullptr, dinvb, (long)Bn*Mm*Hh,
            256, Hh, Hh, Mm, Hh,
            0L, (long)Mm*Hh, (long)Hh*Mm, 0, 0, 0L);
        // S3: hc[b](512x256) = Dinv*(Hc[b](512x128) @ ZT[b](256x128)^T) + bias, fused BN stats
        k_mma2<0,0><<<dim3(4, 4, Bn), 128, SMEM_G>>>(dHc, dZT, dhc,
            dinvd, cbias + (size_t)l*Hh, nullptr, 0L,
            128, Mm, Mm, Hh, Nn,
            (long)Nn*Mm, (long)Hh*Mm, (long)Nn*Hh, 1, 0, 0L);
        k_bnapply_t<<<dim3(Hh/32, Nn/32, Bn), dim3(32, 8)>>>(gam, bet, l, (int)(l == Ll-1));
    }

    k_decoder<<<Bn*Nn/8, 256>>>(Wdec, bdec, out);
}

// round 10
// speedup vs baseline: 7.6287x; 1.0775x over previous
#include <cuda_runtime.h>
#include <cstdint>

#define Bn   64
#define Nn   512
#define Tt   8
#define DINd 2
#define Hh   256
#define Ll   3
#define Ee   8192
#define Mm   128
#define Pout 24
#define EPSf 1e-5f

// ---------------- scratch (allocation-free) ----------------
__device__ float g_h    [Bn*Nn*Hh];
__device__ float g_hs   [Bn*Nn*Hh];
__device__ float g_hsT  [Bn*Hh*Nn];    // h_social^T, fp32
__device__ float g_hc   [Bn*Nn*Hh];
__device__ float g_Yp   [2*Bn*Mm*Hh];  // S1 split-K partials (consumed by S2)
__device__ float g_ZT   [Bn*Hh*Mm];    // (Y @ theta)^T, fp32
__device__ float g_Hc   [Bn*Nn*Mm];    // raw integer counts (tf32-exact)
__device__ float g_HcT  [Bn*Mm*Nn];    // raw integer counts (tf32-exact)
__device__ float g_thT  [Ll*Hh*Hh];    // theta^T, fp32
__device__ float g_invb [Bn*Mm];
__device__ float g_invd [Bn*Nn];
__device__ int   g_cntm [Bn*Mm];
__device__ int   g_cntn [Bn*Nn];
__device__ float g_sum  [Bn*Hh];
__device__ float g_sq   [Bn*Hh];

// ================= helpers =================
__device__ __forceinline__ uint32_t smem_u32(const void* p) {
    uint32_t a;
    asm("{ .reg .u64 t; cvta.to.shared.u64 t, %1; cvt.u32.u64 %0, t; }" : "=r"(a) : "l"(p));
    return a;
}
// lo = v - trunc13(v): exact residual of HW tf32 truncation. (hi operand = raw v.)
__device__ __forceinline__ uint32_t lo_tf32(uint32_t vbits) {
    float hi = __uint_as_float(vbits & 0xffffe000u);
    return __float_as_uint(__uint_as_float(vbits) - hi);
}
#define CP16(dst, src) asm volatile("cp.async.cg.shared.global [%0], [%1], 16;" :: "r"(dst), "l"(src) : "memory")
#define CPCOMMIT()     asm volatile("cp.async.commit_group;" ::: "memory")
#define CPWAIT1()      asm volatile("cp.async.wait_group 1;" ::: "memory")

__device__ __forceinline__ void ldsm4(uint32_t* r, uint32_t addr) {
    asm volatile("ldmatrix.sync.aligned.m8n8.x4.shared.b16 {%0,%1,%2,%3}, [%4];"
        : "=r"(r[0]), "=r"(r[1]), "=r"(r[2]), "=r"(r[3]) : "r"(addr));
}
__device__ __forceinline__ void mma_tf32(float* c, const uint32_t* a, const uint32_t* b) {
    asm volatile(
        "mma.sync.aligned.m16n8k8.row.col.f32.tf32.tf32.f32 "
        "{%0,%1,%2,%3}, {%4,%5,%6,%7}, {%8,%9}, {%0,%1,%2,%3};"
        : "+f"(c[0]), "+f"(c[1]), "+f"(c[2]), "+f"(c[3])
        : "r"(a[0]), "r"(a[1]), "r"(a[2]), "r"(a[3]), "r"(b[0]), "r"(b[1]));
}

// ================= error-compensated tf32 mma.sync GEMM =================
// Block tile 128x64 (M x N), BK=32, 4 warps (2x2), warp tile 64x32.
// fp32 K-major operands; ldmatrix fragment loads; hi = raw bits (HW truncates),
// lo = exact truncation residual via LOP3+FSUB.
// SPLITA=0: C = A@B + A@Blo            (A exact in tf32)
// SPLITA=1: C = A@B + A@Blo + Alo@B
// COMBINE=1: B := (B + B[bOff2]) * rowscaleB[row]   (split-K merge of S1)
// koffY != 0: split-K mode; zstats: blockIdx.y==0 CTAs zero BN stat accumulators.
#define AFL 4096   // A tile floats (128*32)
#define BFL 2048   // B tile floats (64*32)
#define O_B  8192
#define O_B2 12288

template<int SPLITA, int COMBINE>
__global__ void __launch_bounds__(128, 4)
k_mma2(const float* __restrict__ Ag, const float* __restrict__ Bg,
       float* __restrict__ Cg,
       const float* __restrict__ rowscale, const float* __restrict__ bias,
       const float* __restrict__ rowscaleB, long bOff2,
       int K, int lda, int ldb, int N, int M,
       long sA, long sB, long sC, int dostats, int zstats,
       int koffY, long cOffY) {
    extern __shared__ float sm[];
    uint32_t sbase = smem_u32(sm);

    int tid = threadIdx.x, lane = tid & 31, wid = tid >> 5;
    int wm = wid >> 1, wn = wid & 1;
    int col0 = blockIdx.x * 64;
    int row0, k_base;
    long cadd;
    if (koffY) { row0 = 0; k_base = blockIdx.y * koffY; cadd = (long)blockIdx.y * cOffY; }
    else       { row0 = blockIdx.y * 128; k_base = 0; cadd = 0; }
    int z = blockIdx.z;

    if (zstats && blockIdx.y == 0 && tid < 64) {
        g_sum[z * Hh + col0 + tid] = 0.f;
        g_sq [z * Hh + col0 + tid] = 0.f;
    }

    const float* A  = Ag + (size_t)z * sA + k_base;
    const float* B  = Bg + (size_t)z * sB + k_base;
    const float* B2 = COMBINE ? (Bg + bOff2 + (size_t)z * sB + k_base) : nullptr;
    float* C = Cg + (size_t)z * sC + cadd;

    int cr = tid >> 3;                 // cp.async row 0..15
    int cc = (tid & 7) * 4;

    float acc[4][4][4];
#pragma unroll
    for (int i = 0; i < 4; i++)
#pragma unroll
        for (int j = 0; j < 4; j++)
#pragma unroll
            for (int q = 0; q < 4; q++) acc[i][j][q] = 0.f;

    int nkb = K >> 5;
    int g = lane >> 2, t = lane & 3;

    float rsB[4];
    if (COMBINE) {
#pragma unroll
        for (int nf = 0; nf < 4; nf++)
            rsB[nf] = rowscaleB[(size_t)z * Mm + col0 + wn * 32 + nf * 8 + g];
    }

    // ldmatrix per-lane addressing
    int lrow = lane & 7;
    int lsub = lane >> 3;
    uint32_t rm4  = (uint32_t)lrow << 4;
    uint32_t cb4A = (uint32_t)(lsub >> 1) << 4;
    uint32_t cb4B = (uint32_t)(lsub & 1) << 4;
    uint32_t aAddr[4], bAddr[2];
#pragma unroll
    for (int mf = 0; mf < 4; mf++)
        aAddr[mf] = sbase + (uint32_t)((wm * 64 + mf * 16 + ((lsub & 1) << 3) + lrow) << 7);
#pragma unroll
    for (int p = 0; p < 2; p++)
        bAddr[p] = sbase + O_B * 4 + (uint32_t)((wn * 32 + (p * 2 + (lsub >> 1)) * 8 + lrow) << 7);

#pragma unroll
    for (int s = 0; s < 2; s++) {
        int kk = s * 32;
#pragma unroll
        for (int i = 0; i < 8; i++) {             // A: 128 rows
            int rr = cr + i * 16;
            uint32_t so = (uint32_t)(s * AFL + rr * 32 + (cc ^ ((rr & 7) * 4))) * 4;
            CP16(sbase + so, A + (size_t)(row0 + rr) * lda + kk + cc);
        }
#pragma unroll
        for (int i = 0; i < 4; i++) {             // B: 64 rows
            int rr = cr + i * 16;
            uint32_t sw = (uint32_t)(rr * 32 + (cc ^ ((rr & 7) * 4)));
            size_t gb = (size_t)(col0 + rr) * ldb + kk + cc;
            CP16(sbase + (uint32_t)(O_B + s * BFL + sw) * 4, B + gb);
            if (COMBINE) CP16(sbase + (uint32_t)(O_B2 + s * BFL + sw) * 4, B2 + gb);
        }
        CPCOMMIT();
    }

    for (int kb = 0; kb < nkb; kb++) {
        int s = kb & 1;
        CPWAIT1();
        __syncthreads();
        uint32_t aOffS = (uint32_t)(s * AFL) * 4;
        uint32_t bOffS = (uint32_t)(s * BFL) * 4;

#pragma unroll
        for (int ks = 0; ks < 4; ks++) {
            uint32_t ka = (((uint32_t)ks << 5) + cb4A) ^ rm4;
            uint32_t kbo = (((uint32_t)ks << 5) + cb4B) ^ rm4;
            uint32_t a[4][4], bR[4][2], bl[4][2];
#pragma unroll
            for (int mf = 0; mf < 4; mf++)
                ldsm4(a[mf], aAddr[mf] + aOffS + ka);
            {
                uint32_t r[4];
                ldsm4(r, bAddr[0] + bOffS + kbo);
                bR[0][0] = r[0]; bR[0][1] = r[1]; bR[1][0] = r[2]; bR[1][1] = r[3];
                ldsm4(r, bAddr[1] + bOffS + kbo);
                bR[2][0] = r[0]; bR[2][1] = r[1]; bR[3][0] = r[2]; bR[3][1] = r[3];
            }
            if (COMBINE) {
                uint32_t r[4], b2[4][2];
                ldsm4(r, bAddr[0] + (O_B2 - O_B) * 4 + bOffS + kbo);
                b2[0][0] = r[0]; b2[0][1] = r[1]; b2[1][0] = r[2]; b2[1][1] = r[3];
                ldsm4(r, bAddr[1] + (O_B2 - O_B) * 4 + bOffS + kbo);
                b2[2][0] = r[0]; b2[2][1] = r[1]; b2[3][0] = r[2]; b2[3][1] = r[3];
#pragma unroll
                for (int nf = 0; nf < 4; nf++)
#pragma unroll
                    for (int q = 0; q < 2; q++) {
                        float u = (__uint_as_float(bR[nf][q]) + __uint_as_float(b2[nf][q])) * rsB[nf];
                        bR[nf][q] = __float_as_uint(u);
                    }
            }
#pragma unroll
            for (int nf = 0; nf < 4; nf++) {
                bl[nf][0] = lo_tf32(bR[nf][0]);
                bl[nf][1] = lo_tf32(bR[nf][1]);
            }
#pragma unroll
            for (int mf = 0; mf < 4; mf++)
#pragma unroll
                for (int nf = 0; nf < 4; nf++)
                    mma_tf32(acc[mf][nf], a[mf], bR[nf]);
#pragma unroll
            for (int mf = 0; mf < 4; mf++)
#pragma unroll
                for (int nf = 0; nf < 4; nf++)
                    mma_tf32(acc[mf][nf], a[mf], bl[nf]);
            if (SPLITA) {
                uint32_t al[4][4];
#pragma unroll
                for (int mf = 0; mf < 4; mf++)
#pragma unroll
                    for (int q = 0; q < 4; q++)
                        al[mf][q] = lo_tf32(a[mf][q]);
#pragma unroll
                for (int mf = 0; mf < 4; mf++)
#pragma unroll
                    for (int nf = 0; nf < 4; nf++)
                        mma_tf32(acc[mf][nf], al[mf], bR[nf]);
            }
        }
        __syncthreads();

        if (kb + 2 < nkb) {
            int kk = (kb + 2) * 32;
#pragma unroll
            for (int i = 0; i < 8; i++) {
                int rr = cr + i * 16;
                uint32_t so = (uint32_t)(s * AFL + rr * 32 + (cc ^ ((rr & 7) * 4))) * 4;
                CP16(sbase + so, A + (size_t)(row0 + rr) * lda + kk + cc);
            }
#pragma unroll
            for (int i = 0; i < 4; i++) {
                int rr = cr + i * 16;
                uint32_t sw = (uint32_t)(rr * 32 + (cc ^ ((rr & 7) * 4)));
                size_t gb = (size_t)(col0 + rr) * ldb + kk + cc;
                CP16(sbase + (uint32_t)(O_B + s * BFL + sw) * 4, B + gb);
                if (COMBINE) CP16(sbase + (uint32_t)(O_B2 + s * BFL + sw) * 4, B2 + gb);
            }
        }
        CPCOMMIT();
    }

    // ---------------- epilogue ----------------
    const float* rsb = rowscale ? rowscale + (size_t)z * M : nullptr;
    float cs[8], cq[8];
    if (dostats) {
#pragma unroll
        for (int i = 0; i < 8; i++) { cs[i] = 0.f; cq[i] = 0.f; }
    }
#pragma unroll
    for (int mf = 0; mf < 4; mf++) {
        int rr = row0 + wm * 64 + mf * 16 + g;
        float rs0 = rsb ? rsb[rr]     : 1.f;
        float rs1 = rsb ? rsb[rr + 8] : 1.f;
#pragma unroll
        for (int nf = 0; nf < 4; nf++) {
            int ccg = col0 + wn * 32 + nf * 8 + t * 2;
            float c0 = acc[mf][nf][0] * rs0, c1 = acc[mf][nf][1] * rs0;
            float c2 = acc[mf][nf][2] * rs1, c3 = acc[mf][nf][3] * rs1;
            if (bias) {
                float b0 = bias[ccg], b1 = bias[ccg + 1];
                c0 += b0; c1 += b1; c2 += b0; c3 += b1;
            }
            if (dostats) {
                cs[nf*2]   += c0 + c2;  cs[nf*2+1] += c1 + c3;
                cq[nf*2]   += c0*c0 + c2*c2;
                cq[nf*2+1] += c1*c1 + c3*c3;
            }
            *reinterpret_cast<float2*>(&C[(size_t)rr * N + ccg])       = make_float2(c0, c1);
            *reinterpret_cast<float2*>(&C[(size_t)(rr + 8) * N + ccg]) = make_float2(c2, c3);
        }
    }
    if (dostats) {
#pragma unroll
        for (int off = 4; off <= 16; off <<= 1) {
#pragma unroll
            for (int i = 0; i < 8; i++) {
                cs[i] += __shfl_xor_sync(0xffffffffu, cs[i], off);
                cq[i] += __shfl_xor_sync(0xffffffffu, cq[i], off);
            }
        }
        if (g == 0) {
#pragma unroll
            for (int nf = 0; nf < 4; nf++) {
#pragma unroll
                for (int j = 0; j < 2; j++) {
                    int ccg = col0 + wn * 32 + nf * 8 + t * 2 + j;
                    atomicAdd(&g_sum[z * Hh + ccg], cs[nf*2+j]);
                    atomicAdd(&g_sq [z * Hh + ccg], cq[nf*2+j]);
                }
            }
        }
    }
}

// ---------------- encoder ----------------
__global__ void k_encoder(const float* __restrict__ obs,
                          const float* __restrict__ Wenc,
                          const float* __restrict__ benc) {
    int bn = blockIdx.x;
    int h  = threadIdx.x;
    int b  = bn >> 9, n = bn & (Nn - 1);
    __shared__ float srow[Tt*DINd];
    if (h < Tt*DINd) srow[h] = obs[bn*Tt*DINd + h];
    __syncthreads();
    float w0 = Wenc[h], w1 = Wenc[Hh + h], bb = benc[h];
    float acc = 0.f;
#pragma unroll
    for (int t = 0; t < Tt; t++) {
        float v = fmaf(srow[2*t], w0, fmaf(srow[2*t+1], w1, bb));
        acc += fmaxf(v, 0.f);
    }
    float r = acc * (1.f / Tt);
    g_h[(size_t)bn*Hh + h] = r;
    g_hsT[((size_t)b*Hh + h)*Nn + n] = r;
}

// ---------------- incidence build (raw counts) ----------------
__global__ void k_zero_dense() {
    int i = blockIdx.x * blockDim.x + threadIdx.x;
    g_Hc[i]  = 0.f;
    g_HcT[i] = 0.f;
    if (i < Bn*Mm) g_cntm[i] = 0;
    if (i < Bn*Nn) g_cntn[i] = 0;
}
__global__ void k_build(const int* __restrict__ idx) {
    int i = blockIdx.x * blockDim.x + threadIdx.x;
    int b = i >> 13, e = i & (Ee - 1);
    int n = idx[b*2*Ee + e];
    int m = idx[b*2*Ee + Ee + e];
    atomicAdd(&g_Hc [((size_t)b*Nn + n)*Mm + m], 1.f);
    atomicAdd(&g_HcT[((size_t)b*Mm + m)*Nn + n], 1.f);
    atomicAdd(&g_cntn[b*Nn + n], 1);
    atomicAdd(&g_cntm[b*Mm + m], 1);
}
__global__ void k_invdeg() {
    int i = blockIdx.x * blockDim.x + threadIdx.x;
    if (i < Bn*Mm) g_invb[i] = 1.f / fmaxf((float)g_cntm[i], 1.f);
    if (i < Bn*Nn) g_invd[i] = 1.f / fmaxf((float)g_cntn[i], 1.f);
}

// ---------------- theta transpose ----------------
__global__ void k_trans_theta(const float* __restrict__ thetas) {
    __shared__ float t[32][33];
    int l  = blockIdx.z;
    int x0 = blockIdx.x * 32, y0 = blockIdx.y * 32;
    int tx = threadIdx.x, ty = threadIdx.y;
    const float* src = thetas + (size_t)l * Hh * Hh;
#pragma unroll
    for (int j = 0; j < 4; j++)
        t[ty + j*8][tx] = src[(size_t)(y0 + ty + j*8)*Hh + x0 + tx];
    __syncthreads();
#pragma unroll
    for (int j = 0; j < 4; j++)
        g_thT[(size_t)l*Hh*Hh + (size_t)(x0 + ty + j*8)*Hh + y0 + tx] = t[tx][ty + j*8];
}

// ---------------- BN apply + relu -> hsT (or hs row-major on last layer) ----------------
__global__ void k_bnapply_t(const float* __restrict__ gam,
                            const float* __restrict__ bet, int l, int lastLayer) {
    __shared__ float t[32][33];
    int b  = blockIdx.z;
    int h0 = blockIdx.x * 32, n0 = blockIdx.y * 32;
    int tx = threadIdx.x, ty = threadIdx.y;
    int h  = h0 + tx;
    float mean = g_sum[b*Hh + h] * (1.f / Nn);
    float var  = g_sq [b*Hh + h] * (1.f / Nn) - mean*mean;
    float rstd = rsqrtf(var + EPSf);
    float gm = gam[l*Hh + h], bt = bet[l*Hh + h];
#pragma unroll
    for (int j = 0; j < 4; j++) {
        int n = n0 + ty + j*8;
        size_t ix = ((size_t)b*Nn + n)*Hh + h;
        float v = fmaxf((g_hc[ix] - mean) * rstd * gm + bt, 0.f);
        if (lastLayer) g_hs[ix] = v;
        else           t[ty + j*8][tx] = v;
    }
    if (!lastLayer) {
        __syncthreads();
#pragma unroll
        for (int j = 0; j < 4; j++)
            g_hsT[((size_t)b*Hh + h0 + ty + j*8)*Nn + n0 + tx] = t[tx][ty + j*8];
    }
}

// ---------------- decoder ----------------
__global__ void k_decoder(const float* __restrict__ Wdec,
                          const float* __restrict__ bdec,
                          float* __restrict__ out) {
    __shared__ float Ws[Hh*Pout + 32];
    int tid = threadIdx.x;
    for (int i = tid; i < Hh*Pout; i += 256) Ws[i] = Wdec[i];
    __syncthreads();
    int row  = blockIdx.x * 8 + (tid >> 5);
    int lane = tid & 31;
    const float* xh = g_h  + (size_t)row * Hh;
    const float* xs = g_hs + (size_t)row * Hh;
    float xr[8];
#pragma unroll
    for (int j = 0; j < 8; j++) xr[j] = xh[lane + j*32] + xs[lane + j*32];
    float acc = 0.f;
    int wl = (lane < Pout) ? lane : 0;
#pragma unroll 4
    for (int k = 0; k < Hh; k++) {
        float xv = __shfl_sync(0xffffffffu, xr[k >> 5], k & 31);
        acc = fmaf(xv, Ws[k*Pout + wl], acc);
    }
    if (lane < Pout)
        out[(size_t)row*Pout + lane] = acc + bdec[lane];
}

// ---------------- launch ----------------
extern "C" void kernel_launch(void* const* d_in, const int* in_sizes, int n_in,
                              void* d_out, int out_size) {
    const float* obs    = (const float*)d_in[0];
    const int*   idx    = (const int*)  d_in[1];
    const float* Wenc   = (const float*)d_in[2];
    const float* benc   = (const float*)d_in[3];
    const float* thetas = (const float*)d_in[4];
    const float* cbias  = (const float*)d_in[5];
    const float* gam    = (const float*)d_in[6];
    const float* bet    = (const float*)d_in[7];
    const float* Wdec   = (const float*)d_in[8];
    const float* bdec   = (const float*)d_in[9];
    float* out = (float*)d_out;

    float *dHc, *dHcT, *dhsT, *dYp, *dZT, *dhc, *dthT, *dinvb, *dinvd;
    cudaGetSymbolAddress((void**)&dHc,   g_Hc);
    cudaGetSymbolAddress((void**)&dHcT,  g_HcT);
    cudaGetSymbolAddress((void**)&dhsT,  g_hsT);
    cudaGetSymbolAddress((void**)&dYp,   g_Yp);
    cudaGetSymbolAddress((void**)&dZT,   g_ZT);
    cudaGetSymbolAddress((void**)&dhc,   g_hc);
    cudaGetSymbolAddress((void**)&dthT,  g_thT);
    cudaGetSymbolAddress((void**)&dinvb, g_invb);
    cudaGetSymbolAddress((void**)&dinvd, g_invd);

    const int SMEM_G = (2*AFL + 2*BFL) * 4;   // 48KB
    const int SMEM_C = (2*AFL + 4*BFL) * 4;   // 64KB (COMBINE)
    cudaFuncSetAttribute((const void*)k_mma2<0,0>, cudaFuncAttributeMaxDynamicSharedMemorySize, SMEM_G);
    cudaFuncSetAttribute((const void*)k_mma2<1,1>, cudaFuncAttributeMaxDynamicSharedMemorySize, SMEM_C);

    k_encoder<<<Bn*Nn, Hh>>>(obs, Wenc, benc);                     // 1
    k_zero_dense<<<Bn*Nn*Mm/256, 256>>>();                         // 2
    k_build<<<Bn*Ee/256, 256>>>(idx);                              // 3

    for (int l = 0; l < Ll; l++) {
        // S1 split-K (zeroes BN stats): Yp[y] = HcT[:, y*256:+256] @ hsT[:, y*256:+256]^T
        k_mma2<0,0><<<dim3(4, 2, Bn), 128, SMEM_G>>>(dHcT, dhsT, dYp,
            nullptr, nullptr, nullptr, 0L,
            256, Nn, Nn, Hh, Mm,
            (long)Mm*Nn, (long)Hh*Nn, (long)Mm*Hh, 0, 1, 256, (long)Bn*Mm*Hh);
        if (l == 0) {
            k_invdeg<<<(Bn*Nn + 255)/256, 256>>>();
            k_trans_theta<<<dim3(Hh/32, Hh/32, Ll), dim3(32, 8)>>>(thetas);
        }
        // S2: ZT[b](256x128) = thT_l(256x256) @ [invb*(Yp0+Yp1)][b](128x256)^T
        k_mma2<1,1><<<dim3(2, 2, Bn), 128, SMEM_C>>>(dthT + (size_t)l*Hh*Hh, dYp, dZT,
            nullptr, nullptr, dinvb, (long)Bn*Mm*Hh,
            256, Hh, Hh, Mm, Hh,
            0L, (long)Mm*Hh, (long)Hh*Mm, 0, 0, 0, 0L);
        // S3: hc[b](512x256) = Dinv*(Hc[b](512x128) @ ZT[b](256x128)^T) + bias, fused BN stats
        k_mma2<0,0><<<dim3(4, 4, Bn), 128, SMEM_G>>>(dHc, dZT, dhc,
            dinvd, cbias + (size_t)l*Hh, nullptr, 0L,
            128, Mm, Mm, Hh, Nn,
            (long)Nn*Mm, (long)Hh*Mm, (long)Nn*Hh, 1, 0, 0, 0L);
        k_bnapply_t<<<dim3(Hh/32, Nn/32, Bn), dim3(32, 8)>>>(gam, bet, l, (int)(l == Ll-1));
    }

    k_decoder<<<Bn*Nn/8, 256>>>(Wdec, bdec, out);
}

// round 11
// speedup vs baseline: 7.9280x; 1.0392x over previous
#include <cuda_runtime.h>
#include <cstdint>

#define Bn   64
#define Nn   512
#define Tt   8
#define DINd 2
#define Hh   256
#define Ll   3
#define Ee   8192
#define Mm   128
#define Pout 24
#define EPSf 1e-5f

// ---------------- scratch (allocation-free) ----------------
__device__ float g_h    [Bn*Nn*Hh];
__device__ float g_hs   [Bn*Nn*Hh];    // last-layer h_social row-major (decoder)
__device__ float g_hsT  [Bn*Hh*Nn];    // encoder output^T (layer-0 S1 B operand)
__device__ float g_hcT  [Bn*Hh*Nn];    // conv output^T pre-BN (written by S3)
__device__ float g_Yp   [2*Bn*Mm*Hh];  // S1 split-K partials (consumed by S2)
__device__ float g_ZT   [Bn*Hh*Mm];    // (Y @ theta)^T, fp32
__device__ float g_Hc   [Bn*Nn*Mm];    // raw integer counts (tf32-exact)
__device__ float g_HcT  [Bn*Mm*Nn];    // raw integer counts (tf32-exact)
__device__ float g_thT  [Ll*Hh*Hh];    // theta^T, fp32
__device__ float g_invb [Bn*Mm];
__device__ float g_invd [Bn*Nn];
__device__ int   g_cntm [Bn*Mm];
__device__ int   g_cntn [Bn*Nn];
__device__ float g_sum  [Bn*Hh];
__device__ float g_sq   [Bn*Hh];
__device__ float g_bnA  [Bn*Hh];       // BN scale  = rstd*gamma
__device__ float g_bnB  [Bn*Hh];       // BN shift  = beta - mean*scale

// ================= helpers =================
__device__ __forceinline__ uint32_t smem_u32(const void* p) {
    uint32_t a;
    asm("{ .reg .u64 t; cvta.to.shared.u64 t, %1; cvt.u32.u64 %0, t; }" : "=r"(a) : "l"(p));
    return a;
}
// lo = v - trunc13(v): exact residual of HW tf32 truncation. (hi operand = raw v.)
__device__ __forceinline__ uint32_t lo_tf32(uint32_t vbits) {
    float hi = __uint_as_float(vbits & 0xffffe000u);
    return __float_as_uint(__uint_as_float(vbits) - hi);
}
#define CP16(dst, src) asm volatile("cp.async.cg.shared.global [%0], [%1], 16;" :: "r"(dst), "l"(src) : "memory")
#define CPCOMMIT()     asm volatile("cp.async.commit_group;" ::: "memory")
#define CPWAIT1()      asm volatile("cp.async.wait_group 1;" ::: "memory")

__device__ __forceinline__ void ldsm4(uint32_t* r, uint32_t addr) {
    asm volatile("ldmatrix.sync.aligned.m8n8.x4.shared.b16 {%0,%1,%2,%3}, [%4];"
        : "=r"(r[0]), "=r"(r[1]), "=r"(r[2]), "=r"(r[3]) : "r"(addr));
}
__device__ __forceinline__ void mma_tf32(float* c, const uint32_t* a, const uint32_t* b) {
    asm volatile(
        "mma.sync.aligned.m16n8k8.row.col.f32.tf32.tf32.f32 "
        "{%0,%1,%2,%3}, {%4,%5,%6,%7}, {%8,%9}, {%0,%1,%2,%3};"
        : "+f"(c[0]), "+f"(c[1]), "+f"(c[2]), "+f"(c[3])
        : "r"(a[0]), "r"(a[1]), "r"(a[2]), "r"(a[3]), "r"(b[0]), "r"(b[1]));
}

// ================= error-compensated tf32 mma.sync GEMM =================
// Block 128x64 (MxN), BK=32, 4 warps (2x2), warp tile 64x32; ldmatrix loads,
// hi = raw fp32 bits (HW truncates), lo = exact residual.
// SPLITA: also A-lo term. COMBINE: B := (B + B[bOff2]) * rowscaleB[row].
// BNB: B := relu(B*bnA[row] + bnB[row])  (fused BatchNorm+ReLU of prior layer).
// TRANSC: write C transposed ([col][row], ld=N) via smem staging.
// koffY != 0: split-K (blockIdx.y -> K slice + partial C buffer).
// dostats: fused BN column stats. zstats: y==0 CTAs zero the stat buffers.
#define AFL 4096
#define BFL 2048
#define O_B  8192
#define O_B2 12288

template<int SPLITA, int COMBINE, int BNB, int TRANSC>
__global__ void __launch_bounds__(128, 4)
k_mma2(const float* __restrict__ Ag, const float* __restrict__ Bg,
       float* __restrict__ Cg,
       const float* __restrict__ rowscale, const float* __restrict__ bias,
       const float* __restrict__ rowscaleB, long bOff2,
       const float* __restrict__ bnA, const float* __restrict__ bnB,
       int K, int lda, int ldb, int N, int M,
       long sA, long sB, long sC, int dostats, int zstats,
       int koffY, long cOffY) {
    extern __shared__ float sm[];
    uint32_t sbase = smem_u32(sm);

    int tid = threadIdx.x, lane = tid & 31, wid = tid >> 5;
    int wm = wid >> 1, wn = wid & 1;
    int col0 = blockIdx.x * 64;
    int row0, k_base;
    long cadd;
    if (koffY) { row0 = 0; k_base = blockIdx.y * koffY; cadd = (long)blockIdx.y * cOffY; }
    else       { row0 = blockIdx.y * 128; k_base = 0; cadd = 0; }
    int z = blockIdx.z;

    if (zstats && blockIdx.y == 0 && tid < 64) {
        g_sum[z * Hh + col0 + tid] = 0.f;
        g_sq [z * Hh + col0 + tid] = 0.f;
    }

    const float* A  = Ag + (size_t)z * sA + k_base;
    const float* B  = Bg + (size_t)z * sB + k_base;
    const float* B2 = COMBINE ? (Bg + bOff2 + (size_t)z * sB + k_base) : nullptr;
    float* C = Cg + (size_t)z * sC + cadd;

    int cr = tid >> 3;
    int cc = (tid & 7) * 4;

    float acc[4][4][4];
#pragma unroll
    for (int i = 0; i < 4; i++)
#pragma unroll
        for (int j = 0; j < 4; j++)
#pragma unroll
            for (int q = 0; q < 4; q++) acc[i][j][q] = 0.f;

    int nkb = K >> 5;
    int g = lane >> 2, t = lane & 3;

    float rsB[4], bAc[4], bBc[4];
    if (COMBINE) {
#pragma unroll
        for (int nf = 0; nf < 4; nf++)
            rsB[nf] = rowscaleB[(size_t)z * Mm + col0 + wn * 32 + nf * 8 + g];
    }
    if (BNB) {
#pragma unroll
        for (int nf = 0; nf < 4; nf++) {
            int idx = z * Hh + col0 + wn * 32 + nf * 8 + g;
            bAc[nf] = bnA[idx];
            bBc[nf] = bnB[idx];
        }
    }

    // ldmatrix per-lane addressing
    int lrow = lane & 7;
    int lsub = lane >> 3;
    uint32_t rm4  = (uint32_t)lrow << 4;
    uint32_t cb4A = (uint32_t)(lsub >> 1) << 4;
    uint32_t cb4B = (uint32_t)(lsub & 1) << 4;
    uint32_t aAddr[4], bAddr[2];
#pragma unroll
    for (int mf = 0; mf < 4; mf++)
        aAddr[mf] = sbase + (uint32_t)((wm * 64 + mf * 16 + ((lsub & 1) << 3) + lrow) << 7);
#pragma unroll
    for (int p = 0; p < 2; p++)
        bAddr[p] = sbase + O_B * 4 + (uint32_t)((wn * 32 + (p * 2 + (lsub >> 1)) * 8 + lrow) << 7);

#pragma unroll
    for (int s = 0; s < 2; s++) {
        int kk = s * 32;
#pragma unroll
        for (int i = 0; i < 8; i++) {
            int rr = cr + i * 16;
            uint32_t so = (uint32_t)(s * AFL + rr * 32 + (cc ^ ((rr & 7) * 4))) * 4;
            CP16(sbase + so, A + (size_t)(row0 + rr) * lda + kk + cc);
        }
#pragma unroll
        for (int i = 0; i < 4; i++) {
            int rr = cr + i * 16;
            uint32_t sw = (uint32_t)(rr * 32 + (cc ^ ((rr & 7) * 4)));
            size_t gb = (size_t)(col0 + rr) * ldb + kk + cc;
            CP16(sbase + (uint32_t)(O_B + s * BFL + sw) * 4, B + gb);
            if (COMBINE) CP16(sbase + (uint32_t)(O_B2 + s * BFL + sw) * 4, B2 + gb);
        }
        CPCOMMIT();
    }

    for (int kb = 0; kb < nkb; kb++) {
        int s = kb & 1;
        CPWAIT1();
        __syncthreads();
        uint32_t aOffS = (uint32_t)(s * AFL) * 4;
        uint32_t bOffS = (uint32_t)(s * BFL) * 4;

#pragma unroll
        for (int ks = 0; ks < 4; ks++) {
            uint32_t ka  = (((uint32_t)ks << 5) + cb4A) ^ rm4;
            uint32_t kbo = (((uint32_t)ks << 5) + cb4B) ^ rm4;
            uint32_t a[4][4], bR[4][2], bl[4][2];
#pragma unroll
            for (int mf = 0; mf < 4; mf++)
                ldsm4(a[mf], aAddr[mf] + aOffS + ka);
            {
                uint32_t r[4];
                ldsm4(r, bAddr[0] + bOffS + kbo);
                bR[0][0] = r[0]; bR[0][1] = r[1]; bR[1][0] = r[2]; bR[1][1] = r[3];
                ldsm4(r, bAddr[1] + bOffS + kbo);
                bR[2][0] = r[0]; bR[2][1] = r[1]; bR[3][0] = r[2]; bR[3][1] = r[3];
            }
            if (COMBINE) {
                uint32_t r[4], b2[4][2];
                ldsm4(r, bAddr[0] + (O_B2 - O_B) * 4 + bOffS + kbo);
                b2[0][0] = r[0]; b2[0][1] = r[1]; b2[1][0] = r[2]; b2[1][1] = r[3];
                ldsm4(r, bAddr[1] + (O_B2 - O_B) * 4 + bOffS + kbo);
                b2[2][0] = r[0]; b2[2][1] = r[1]; b2[3][0] = r[2]; b2[3][1] = r[3];
#pragma unroll
                for (int nf = 0; nf < 4; nf++)
#pragma unroll
                    for (int q = 0; q < 2; q++) {
                        float u = (__uint_as_float(bR[nf][q]) + __uint_as_float(b2[nf][q])) * rsB[nf];
                        bR[nf][q] = __float_as_uint(u);
                    }
            }
            if (BNB) {
#pragma unroll
                for (int nf = 0; nf < 4; nf++)
#pragma unroll
                    for (int q = 0; q < 2; q++) {
                        float u = fmaxf(fmaf(__uint_as_float(bR[nf][q]), bAc[nf], bBc[nf]), 0.f);
                        bR[nf][q] = __float_as_uint(u);
                    }
            }
#pragma unroll
            for (int nf = 0; nf < 4; nf++) {
                bl[nf][0] = lo_tf32(bR[nf][0]);
                bl[nf][1] = lo_tf32(bR[nf][1]);
            }
#pragma unroll
            for (int mf = 0; mf < 4; mf++)
#pragma unroll
                for (int nf = 0; nf < 4; nf++)
                    mma_tf32(acc[mf][nf], a[mf], bR[nf]);
#pragma unroll
            for (int mf = 0; mf < 4; mf++)
#pragma unroll
                for (int nf = 0; nf < 4; nf++)
                    mma_tf32(acc[mf][nf], a[mf], bl[nf]);
            if (SPLITA) {
                uint32_t al[4][4];
#pragma unroll
                for (int mf = 0; mf < 4; mf++)
#pragma unroll
                    for (int q = 0; q < 4; q++)
                        al[mf][q] = lo_tf32(a[mf][q]);
#pragma unroll
                for (int mf = 0; mf < 4; mf++)
#pragma unroll
                    for (int nf = 0; nf < 4; nf++)
                        mma_tf32(acc[mf][nf], al[mf], bR[nf]);
            }
        }
        __syncthreads();

        if (kb + 2 < nkb) {
            int kk = (kb + 2) * 32;
#pragma unroll
            for (int i = 0; i < 8; i++) {
                int rr = cr + i * 16;
                uint32_t so = (uint32_t)(s * AFL + rr * 32 + (cc ^ ((rr & 7) * 4))) * 4;
                CP16(sbase + so, A + (size_t)(row0 + rr) * lda + kk + cc);
            }
#pragma unroll
            for (int i = 0; i < 4; i++) {
                int rr = cr + i * 16;
                uint32_t sw = (uint32_t)(rr * 32 + (cc ^ ((rr & 7) * 4)));
                size_t gb = (size_t)(col0 + rr) * ldb + kk + cc;
                CP16(sbase + (uint32_t)(O_B + s * BFL + sw) * 4, B + gb);
                if (COMBINE) CP16(sbase + (uint32_t)(O_B2 + s * BFL + sw) * 4, B2 + gb);
            }
        }
        CPCOMMIT();
    }

    // ---------------- epilogue ----------------
    const float* rsb = rowscale ? rowscale + (size_t)z * M : nullptr;
    float cs[8], cq[8];
    if (dostats) {
#pragma unroll
        for (int i = 0; i < 8; i++) { cs[i] = 0.f; cq[i] = 0.f; }
    }
    if (TRANSC) __syncthreads();      // smem stage buffers reused below

#pragma unroll
    for (int mf = 0; mf < 4; mf++) {
        int rl = wm * 64 + mf * 16 + g;
        int rr = row0 + rl;
        float rs0 = rsb ? rsb[rr]     : 1.f;
        float rs1 = rsb ? rsb[rr + 8] : 1.f;
#pragma unroll
        for (int nf = 0; nf < 4; nf++) {
            int cl  = wn * 32 + nf * 8 + t * 2;
            int ccg = col0 + cl;
            float c0 = acc[mf][nf][0] * rs0, c1 = acc[mf][nf][1] * rs0;
            float c2 = acc[mf][nf][2] * rs1, c3 = acc[mf][nf][3] * rs1;
            if (bias) {
                float b0 = bias[ccg], b1 = bias[ccg + 1];
                c0 += b0; c1 += b1; c2 += b0; c3 += b1;
            }
            if (dostats) {
                cs[nf*2]   += c0 + c2;  cs[nf*2+1] += c1 + c3;
                cq[nf*2]   += c0*c0 + c2*c2;
                cq[nf*2+1] += c1*c1 + c3*c3;
            }
            if (TRANSC) {
                sm[cl       * 132 + rl    ] = c0;
                sm[(cl + 1) * 132 + rl    ] = c1;
                sm[cl       * 132 + rl + 8] = c2;
                sm[(cl + 1) * 132 + rl + 8] = c3;
            } else {
                *reinterpret_cast<float2*>(&C[(size_t)rr * N + ccg])       = make_float2(c0, c1);
                *reinterpret_cast<float2*>(&C[(size_t)(rr + 8) * N + ccg]) = make_float2(c2, c3);
            }
        }
    }
    if (TRANSC) {
        __syncthreads();
        for (int i = tid; i < 64 * 32; i += 128) {
            int h  = i >> 5;
            int n4 = (i & 31) << 2;
            float4 v = *reinterpret_cast<float4*>(&sm[h * 132 + n4]);
            *reinterpret_cast<float4*>(&C[(size_t)(col0 + h) * N + row0 + n4]) = v;
        }
    }
    if (dostats) {
#pragma unroll
        for (int off = 4; off <= 16; off <<= 1) {
#pragma unroll
            for (int i = 0; i < 8; i++) {
                cs[i] += __shfl_xor_sync(0xffffffffu, cs[i], off);
                cq[i] += __shfl_xor_sync(0xffffffffu, cq[i], off);
            }
        }
        if (g == 0) {
#pragma unroll
            for (int nf = 0; nf < 4; nf++) {
#pragma unroll
                for (int j = 0; j < 2; j++) {
                    int ccg = col0 + wn * 32 + nf * 8 + t * 2 + j;
                    atomicAdd(&g_sum[z * Hh + ccg], cs[nf*2+j]);
                    atomicAdd(&g_sq [z * Hh + ccg], cq[nf*2+j]);
                }
            }
        }
    }
}

// ---------------- encoder ----------------
__global__ void k_encoder(const float* __restrict__ obs,
                          const float* __restrict__ Wenc,
                          const float* __restrict__ benc) {
    int bn = blockIdx.x;
    int h  = threadIdx.x;
    int b  = bn >> 9, n = bn & (Nn - 1);
    __shared__ float srow[Tt*DINd];
    if (h < Tt*DINd) srow[h] = obs[bn*Tt*DINd + h];
    __syncthreads();
    float w0 = Wenc[h], w1 = Wenc[Hh + h], bb = benc[h];
    float acc = 0.f;
#pragma unroll
    for (int t = 0; t < Tt; t++) {
        float v = fmaf(srow[2*t], w0, fmaf(srow[2*t+1], w1, bb));
        acc += fmaxf(v, 0.f);
    }
    float r = acc * (1.f / Tt);
    g_h[(size_t)bn*Hh + h] = r;
    g_hsT[((size_t)b*Hh + h)*Nn + n] = r;
}

// ---------------- incidence build (raw counts) ----------------
__global__ void k_zero_dense() {
    int i = blockIdx.x * blockDim.x + threadIdx.x;
    g_Hc[i]  = 0.f;
    g_HcT[i] = 0.f;
    if (i < Bn*Mm) g_cntm[i] = 0;
    if (i < Bn*Nn) g_cntn[i] = 0;
}
__global__ void k_build(const int* __restrict__ idx) {
    int i = blockIdx.x * blockDim.x + threadIdx.x;
    int b = i >> 13, e = i & (Ee - 1);
    int n = idx[b*2*Ee + e];
    int m = idx[b*2*Ee + Ee + e];
    atomicAdd(&g_Hc [((size_t)b*Nn + n)*Mm + m], 1.f);
    atomicAdd(&g_HcT[((size_t)b*Mm + m)*Nn + n], 1.f);
    atomicAdd(&g_cntn[b*Nn + n], 1);
    atomicAdd(&g_cntm[b*Mm + m], 1);
}
__global__ void k_invdeg() {
    int i = blockIdx.x * blockDim.x + threadIdx.x;
    if (i < Bn*Mm) g_invb[i] = 1.f / fmaxf((float)g_cntm[i], 1.f);
    if (i < Bn*Nn) g_invd[i] = 1.f / fmaxf((float)g_cntn[i], 1.f);
}

// ---------------- theta transpose ----------------
__global__ void k_trans_theta(const float* __restrict__ thetas) {
    __shared__ float t[32][33];
    int l  = blockIdx.z;
    int x0 = blockIdx.x * 32, y0 = blockIdx.y * 32;
    int tx = threadIdx.x, ty = threadIdx.y;
    const float* src = thetas + (size_t)l * Hh * Hh;
#pragma unroll
    for (int j = 0; j < 4; j++)
        t[ty + j*8][tx] = src[(size_t)(y0 + ty + j*8)*Hh + x0 + tx];
    __syncthreads();
#pragma unroll
    for (int j = 0; j < 4; j++)
        g_thT[(size_t)l*Hh*Hh + (size_t)(x0 + ty + j*8)*Hh + y0 + tx] = t[tx][ty + j*8];
}

// ---------------- BN finalize: stats -> per-(b,h) scale/shift ----------------
__global__ void k_bnfin(const float* __restrict__ gam,
                        const float* __restrict__ bet, int l) {
    int i = blockIdx.x * 256 + threadIdx.x;   // over Bn*Hh
    int h = i & (Hh - 1);
    float mean = g_sum[i] * (1.f / Nn);
    float var  = g_sq [i] * (1.f / Nn) - mean * mean;
    float sc = rsqrtf(var + EPSf) * gam[l*Hh + h];
    g_bnA[i] = sc;
    g_bnB[i] = bet[l*Hh + h] - mean * sc;
}

// ---------------- last-layer BN apply: hcT -> hs row-major ----------------
__global__ void k_bn_last() {
    __shared__ float t[32][33];
    int b  = blockIdx.z;
    int h0 = blockIdx.x * 32, n0 = blockIdx.y * 32;
    int tx = threadIdx.x, ty = threadIdx.y;
#pragma unroll
    for (int j = 0; j < 4; j++) {
        int h = h0 + ty + j*8;
        float v = g_hcT[((size_t)b*Hh + h)*Nn + n0 + tx];
        t[ty + j*8][tx] = fmaxf(fmaf(v, g_bnA[b*Hh + h], g_bnB[b*Hh + h]), 0.f);
    }
    __syncthreads();
#pragma unroll
    for (int j = 0; j < 4; j++)
        g_hs[((size_t)b*Nn + n0 + ty + j*8)*Hh + h0 + tx] = t[tx][ty + j*8];
}

// ---------------- decoder ----------------
__global__ void k_decoder(const float* __restrict__ Wdec,
                          const float* __restrict__ bdec,
                          float* __restrict__ out) {
    __shared__ float Ws[Hh*Pout + 32];
    int tid = threadIdx.x;
    for (int i = tid; i < Hh*Pout; i += 256) Ws[i] = Wdec[i];
    __syncthreads();
    int row  = blockIdx.x * 8 + (tid >> 5);
    int lane = tid & 31;
    const float* xh = g_h  + (size_t)row * Hh;
    const float* xs = g_hs + (size_t)row * Hh;
    float xr[8];
#pragma unroll
    for (int j = 0; j < 8; j++) xr[j] = xh[lane + j*32] + xs[lane + j*32];
    float acc = 0.f;
    int wl = (lane < Pout) ? lane : 0;
#pragma unroll 4
    for (int k = 0; k < Hh; k++) {
        float xv = __shfl_sync(0xffffffffu, xr[k >> 5], k & 31);
        acc = fmaf(xv, Ws[k*Pout + wl], acc);
    }
    if (lane < Pout)
        out[(size_t)row*Pout + lane] = acc + bdec[lane];
}

// ---------------- launch ----------------
extern "C" void kernel_launch(void* const* d_in, const int* in_sizes, int n_in,
                              void* d_out, int out_size) {
    const float* obs    = (const float*)d_in[0];
    const int*   idx    = (const int*)  d_in[1];
    const float* Wenc   = (const float*)d_in[2];
    const float* benc   = (const float*)d_in[3];
    const float* thetas = (const float*)d_in[4];
    const float* cbias  = (const float*)d_in[5];
    const float* gam    = (const float*)d_in[6];
    const float* bet    = (const float*)d_in[7];
    const float* Wdec   = (const float*)d_in[8];
    const float* bdec   = (const float*)d_in[9];
    float* out = (float*)d_out;

    float *dHc, *dHcT, *dhsT, *dhcT, *dYp, *dZT, *dthT, *dinvb, *dinvd, *dbnA, *dbnB;
    cudaGetSymbolAddress((void**)&dHc,   g_Hc);
    cudaGetSymbolAddress((void**)&dHcT,  g_HcT);
    cudaGetSymbolAddress((void**)&dhsT,  g_hsT);
    cudaGetSymbolAddress((void**)&dhcT,  g_hcT);
    cudaGetSymbolAddress((void**)&dYp,   g_Yp);
    cudaGetSymbolAddress((void**)&dZT,   g_ZT);
    cudaGetSymbolAddress((void**)&dthT,  g_thT);
    cudaGetSymbolAddress((void**)&dinvb, g_invb);
    cudaGetSymbolAddress((void**)&dinvd, g_invd);
    cudaGetSymbolAddress((void**)&dbnA,  g_bnA);
    cudaGetSymbolAddress((void**)&dbnB,  g_bnB);

    const int SMEM_G = (2*AFL + 2*BFL) * 4;   // 48KB
    const int SMEM_C = (2*AFL + 4*BFL) * 4;   // 64KB (COMBINE)
    cudaFuncSetAttribute((const void*)k_mma2<0,0,0,0>, cudaFuncAttributeMaxDynamicSharedMemorySize, SMEM_G);
    cudaFuncSetAttribute((const void*)k_mma2<0,0,1,0>, cudaFuncAttributeMaxDynamicSharedMemorySize, SMEM_G);
    cudaFuncSetAttribute((const void*)k_mma2<1,1,0,0>, cudaFuncAttributeMaxDynamicSharedMemorySize, SMEM_C);
    cudaFuncSetAttribute((const void*)k_mma2<0,0,0,1>, cudaFuncAttributeMaxDynamicSharedMemorySize, SMEM_G);

    k_encoder<<<Bn*Nn, Hh>>>(obs, Wenc, benc);
    k_zero_dense<<<Bn*Nn*Mm/256, 256>>>();
    k_build<<<Bn*Ee/256, 256>>>(idx);

    for (int l = 0; l < Ll; l++) {
        // S1 split-K (zeroes BN stats): Yp[y] = HcT @ Bsrc^T over K-slice y
        // Bsrc = hsT (layer 0) or relu(BN(hcT)) on the fly (layers 1,2)
        if (l == 0) {
            k_mma2<0,0,0,0><<<dim3(4, 2, Bn), 128, SMEM_G>>>(dHcT, dhsT, dYp,
                nullptr, nullptr, nullptr, 0L, nullptr, nullptr,
                256, Nn, Nn, Hh, Mm,
                (long)Mm*Nn, (long)Hh*Nn, (long)Mm*Hh, 0, 1, 256, (long)Bn*Mm*Hh);
            k_invdeg<<<(Bn*Nn + 255)/256, 256>>>();
            k_trans_theta<<<dim3(Hh/32, Hh/32, Ll), dim3(32, 8)>>>(thetas);
        } else {
            k_mma2<0,0,1,0><<<dim3(4, 2, Bn), 128, SMEM_G>>>(dHcT, dhcT, dYp,
                nullptr, nullptr, nullptr, 0L, dbnA, dbnB,
                256, Nn, Nn, Hh, Mm,
                (long)Mm*Nn, (long)Hh*Nn, (long)Mm*Hh, 0, 1, 256, (long)Bn*Mm*Hh);
        }
        // S2: ZT[b](256x128) = thT_l(256x256) @ [invb*(Yp0+Yp1)][b](128x256)^T
        k_mma2<1,1,0,0><<<dim3(2, 2, Bn), 128, SMEM_C>>>(dthT + (size_t)l*Hh*Hh, dYp, dZT,
            nullptr, nullptr, dinvb, (long)Bn*Mm*Hh, nullptr, nullptr,
            256, Hh, Hh, Mm, Hh,
            0L, (long)Mm*Hh, (long)Hh*Mm, 0, 0, 0, 0L);
        // S3: hcT[b] = (Dinv*(Hc @ ZT^T) + bias)^T, fused BN stats, transposed write
        k_mma2<0,0,0,1><<<dim3(4, 4, Bn), 128, SMEM_G>>>(dHc, dZT, dhcT,
            dinvd, cbias + (size_t)l*Hh, nullptr, 0L, nullptr, nullptr,
            128, Mm, Mm, Nn, Nn,
            (long)Nn*Mm, (long)Hh*Mm, (long)Hh*Nn, 1, 0, 0, 0L);
        k_bnfin<<<Bn*Hh/256, 256>>>(gam, bet, l);
    }

    k_bn_last<<<dim3(Hh/32, Nn/32, Bn), dim3(32, 8)>>>();
    k_decoder<<<Bn*Nn/8, 256>>>(Wdec, bdec, out);
}